// round 1
// baseline (speedup 1.0000x reference)
#include <cuda_runtime.h>
#include <cuda_bf16.h>
#include <math.h>

// ---------------- model constants ----------------
#define BDIM   8
#define TTXT   64
#define TSEQ   256
#define TTOT   320            // 64 + 256
#define MROWS  (BDIM*TTOT)    // 2560
#define DIM    1024
#define LDIMC  128
#define FFN    4096
#define HEADS  16
#define HDIM   64
#define NLAYER 4
#define HID    1024
#define KF1    (DIM + LDIMC + 2)   // 1154
#define NSTEPS 16

// ---------------- scratch (device globals; no allocations allowed) ----------------
__device__ float g_seqf[BDIM*TSEQ*LDIMC];     // nan-fixed sequence
__device__ float g_x   [BDIM*TSEQ*DIM];       // seq @ W_in
__device__ float g_h   [MROWS*DIM];           // residual stream
__device__ float g_tmp [MROWS*DIM];           // LN outputs
__device__ float g_qkv [MROWS*3*DIM];
__device__ float g_att [MROWS*DIM];
__device__ float g_mid [MROWS*FFN];
__device__ float g_last[BDIM*DIM];
__device__ float g_cur [BDIM*LDIMC];
__device__ float g_inp [BDIM*KF1];
__device__ float g_f1  [BDIM*HID];
__device__ float g_f2  [BDIM*HID];

// ---------------- helpers ----------------
__device__ __forceinline__ float gelu_tanh(float x) {
    const float c = 0.7978845608028654f;
    float t = c * (x + 0.044715f * x * x * x);
    return 0.5f * x * (1.0f + tanhf(t));
}
__device__ __forceinline__ float silu(float x) {
    return x / (1.0f + __expf(-x));
}

// ---------------- elementwise / setup kernels ----------------
__global__ void nanfix_kernel(const float* __restrict__ seq,
                              const float* __restrict__ bos,
                              float* __restrict__ out, int n) {
    int i = blockIdx.x * blockDim.x + threadIdx.x;
    if (i < n) {
        float v = seq[i];
        out[i] = (v != v) ? bos[i & (LDIMC - 1)] : v;
    }
}

// build h = concat([text_embeddings, x], axis=1) ; float4 granularity
__global__ void concat_kernel(const float* __restrict__ text,
                              const float* __restrict__ x,
                              float* __restrict__ h) {
    int idx = blockIdx.x * blockDim.x + threadIdx.x;   // float4 index
    int row = idx >> 8;                                 // 256 float4 per row
    int c4  = idx & 255;
    if (row >= MROWS) return;
    int b = row / TTOT, t = row - b * TTOT;
    float4 v;
    if (t < TTXT)
        v = ((const float4*)text)[(size_t)(b * TTXT + t) * 256 + c4];
    else
        v = ((const float4*)x)[(size_t)(b * TSEQ + (t - TTXT)) * 256 + c4];
    ((float4*)h)[(size_t)row * 256 + c4] = v;
}

// ---------------- LayerNorm: one block per row (N=1024) ----------------
__global__ void __launch_bounds__(256) layernorm_kernel(
        const float* __restrict__ in, float* __restrict__ out,
        const float* __restrict__ g, const float* __restrict__ bta) {
    int row = blockIdx.x;
    int tid = threadIdx.x;
    const float4* in4 = (const float4*)(in + (size_t)row * DIM);
    float4 v = in4[tid];
    float s  = v.x + v.y + v.z + v.w;
    float ss = v.x*v.x + v.y*v.y + v.z*v.z + v.w*v.w;
    // warp reduce
    #pragma unroll
    for (int o = 16; o; o >>= 1) {
        s  += __shfl_xor_sync(0xffffffffu, s,  o);
        ss += __shfl_xor_sync(0xffffffffu, ss, o);
    }
    __shared__ float sh[16];
    int w = tid >> 5, l = tid & 31;
    if (l == 0) { sh[w] = s; sh[8 + w] = ss; }
    __syncthreads();
    float S = 0.f, SS = 0.f;
    #pragma unroll
    for (int i = 0; i < 8; i++) { S += sh[i]; SS += sh[8 + i]; }
    float mean = S * (1.0f / DIM);
    float var  = SS * (1.0f / DIM) - mean * mean;
    float rs   = rsqrtf(var + 1e-5f);
    float4 gg = ((const float4*)g)[tid];
    float4 bb = ((const float4*)bta)[tid];
    float4 o4;
    o4.x = (v.x - mean) * rs * gg.x + bb.x;
    o4.y = (v.y - mean) * rs * gg.y + bb.y;
    o4.z = (v.z - mean) * rs * gg.z + bb.z;
    o4.w = (v.w - mean) * rs * gg.w + bb.w;
    ((float4*)(out + (size_t)row * DIM))[tid] = o4;
}

// ---------------- SGEMM: C = epi(A@B + bias [, res]) ----------------
// A: MxK row-major, B: KxN row-major. M,N multiples of 128; K multiple of 8.
// epi: 0 = bias ; 1 = bias+gelu ; 2 = bias+residual
__global__ void __launch_bounds__(256) sgemm_kernel(
        const float* __restrict__ A, const float* __restrict__ B,
        const float* __restrict__ bias, const float* __restrict__ res,
        float* __restrict__ C, int M, int N, int K, int epi) {
    __shared__ float As[2][8][128];
    __shared__ float Bs[2][8][128];
    const int tid = threadIdx.x;
    const int bm = blockIdx.y * 128;
    const int bn = blockIdx.x * 128;

    const int arow = tid >> 1, acol = (tid & 1) << 2;
    const int brow = tid >> 5, bcol = (tid & 31) << 2;
    const float* Ap = A + (size_t)(bm + arow) * K + acol;
    const float* Bp = B + (size_t)brow * N + bn + bcol;

    float4 a4 = *(const float4*)Ap;
    float4 b4 = *(const float4*)Bp;
    As[0][acol+0][arow] = a4.x; As[0][acol+1][arow] = a4.y;
    As[0][acol+2][arow] = a4.z; As[0][acol+3][arow] = a4.w;
    *(float4*)&Bs[0][brow][bcol] = b4;
    __syncthreads();

    float acc[8][8] = {};
    const int tx = (tid & 15) << 2;
    const int ty = (tid >> 4) << 2;
    const int nk = K >> 3;

    for (int kt = 0; kt < nk; kt++) {
        int cur = kt & 1, nxt = cur ^ 1;
        if (kt + 1 < nk) {
            a4 = *(const float4*)(Ap + (size_t)(kt + 1) * 8);
            b4 = *(const float4*)(Bp + (size_t)(kt + 1) * 8 * N);
        }
        #pragma unroll
        for (int k = 0; k < 8; k++) {
            float4 a0 = *(const float4*)&As[cur][k][ty];
            float4 a1 = *(const float4*)&As[cur][k][ty + 64];
            float4 b0 = *(const float4*)&Bs[cur][k][tx];
            float4 b1 = *(const float4*)&Bs[cur][k][tx + 64];
            float ar[8] = {a0.x,a0.y,a0.z,a0.w,a1.x,a1.y,a1.z,a1.w};
            float br[8] = {b0.x,b0.y,b0.z,b0.w,b1.x,b1.y,b1.z,b1.w};
            #pragma unroll
            for (int i = 0; i < 8; i++)
                #pragma unroll
                for (int j = 0; j < 8; j++)
                    acc[i][j] = fmaf(ar[i], br[j], acc[i][j]);
        }
        if (kt + 1 < nk) {
            __syncthreads();
            As[nxt][acol+0][arow] = a4.x; As[nxt][acol+1][arow] = a4.y;
            As[nxt][acol+2][arow] = a4.z; As[nxt][acol+3][arow] = a4.w;
            *(float4*)&Bs[nxt][brow][bcol] = b4;
            __syncthreads();
        }
    }

    #pragma unroll
    for (int i = 0; i < 8; i++) {
        int gm = bm + ty + (i & 3) + ((i >> 2) << 6);
        size_t rowoff = (size_t)gm * N;
        #pragma unroll
        for (int jh = 0; jh < 2; jh++) {
            int gn = bn + tx + (jh << 6);
            float4 v;
            v.x = acc[i][jh*4+0] + bias[gn+0];
            v.y = acc[i][jh*4+1] + bias[gn+1];
            v.z = acc[i][jh*4+2] + bias[gn+2];
            v.w = acc[i][jh*4+3] + bias[gn+3];
            if (epi == 1) {
                v.x = gelu_tanh(v.x); v.y = gelu_tanh(v.y);
                v.z = gelu_tanh(v.z); v.w = gelu_tanh(v.w);
            } else if (epi == 2) {
                float4 r = *(const float4*)&res[rowoff + gn];
                v.x += r.x; v.y += r.y; v.z += r.z; v.w += r.w;
            }
            *(float4*)&C[rowoff + gn] = v;
        }
    }
}

// ---------------- causal attention (fp32, flash-style) ----------------
// grid: (5 qtiles of 64, HEADS, BDIM), block: 64 threads (1 query each)
__global__ void __launch_bounds__(64) attn_kernel(
        const float* __restrict__ qkv, float* __restrict__ o) {
    const int qt = blockIdx.x;
    const int h  = blockIdx.y;
    const int b  = blockIdx.z;
    const int tq = threadIdx.x;
    const int q  = qt * 64 + tq;

    __shared__ float Ks[32][68];
    __shared__ float Vs[32][68];
    __shared__ float Sb[64][33];

    float qreg[HDIM], acc[HDIM];
    const float* qp = qkv + (size_t)(b * TTOT + q) * (3 * DIM) + h * HDIM;
    #pragma unroll
    for (int d4 = 0; d4 < 16; d4++) {
        float4 v = ((const float4*)qp)[d4];
        qreg[4*d4+0] = v.x; qreg[4*d4+1] = v.y; qreg[4*d4+2] = v.z; qreg[4*d4+3] = v.w;
    }
    #pragma unroll
    for (int d = 0; d < HDIM; d++) acc[d] = 0.f;
    float mrun = -1e30f, lrun = 0.f;

    const int nkt = 2 * qt + 2;     // tiles of 32 keys covering [0, qt*64+64)
    for (int kt = 0; kt < nkt; kt++) {
        // cooperative load: threads 0-31 -> K rows, 32-63 -> V rows
        {
            int r = tq & 31;
            bool isV = (tq >= 32);
            const float* p = qkv + (size_t)(b * TTOT + kt * 32 + r) * (3 * DIM)
                             + (isV ? 2 * DIM : DIM) + h * HDIM;
            float* dst = isV ? &Vs[r][0] : &Ks[r][0];
            #pragma unroll
            for (int d4 = 0; d4 < 16; d4++)
                ((float4*)dst)[d4] = ((const float4*)p)[d4];
        }
        __syncthreads();

        // scores for this tile
        for (int j = 0; j < 32; j++) {
            float s = 0.f;
            #pragma unroll
            for (int d = 0; d < HDIM; d++) s = fmaf(qreg[d], Ks[j][d], s);
            s *= 0.125f;   // 1/sqrt(64)
            int kg = kt * 32 + j;
            Sb[tq][j] = (kg <= q) ? s : -1e30f;
        }
        float tmax = -1e30f;
        #pragma unroll
        for (int j = 0; j < 32; j++) tmax = fmaxf(tmax, Sb[tq][j]);
        float mnew = fmaxf(mrun, tmax);
        float corr = __expf(mrun - mnew);
        lrun *= corr;
        #pragma unroll
        for (int d = 0; d < HDIM; d++) acc[d] *= corr;
        for (int j = 0; j < 32; j++) {
            float p = __expf(Sb[tq][j] - mnew);
            lrun += p;
            #pragma unroll
            for (int d = 0; d < HDIM; d++) acc[d] = fmaf(p, Vs[j][d], acc[d]);
        }
        mrun = mnew;
        __syncthreads();
    }

    float inv = 1.0f / lrun;
    float* op = o + (size_t)(b * TTOT + q) * DIM + h * HDIM;
    #pragma unroll
    for (int d4 = 0; d4 < 16; d4++) {
        float4 v;
        v.x = acc[4*d4+0]*inv; v.y = acc[4*d4+1]*inv;
        v.z = acc[4*d4+2]*inv; v.w = acc[4*d4+3]*inv;
        ((float4*)op)[d4] = v;
    }
}

// ---------------- finalize: last token, eos, current init ----------------
__global__ void __launch_bounds__(256) finalize_kernel(
        const float* __restrict__ hn, const float* __restrict__ noise,
        const float* __restrict__ Weos, const float* __restrict__ beos,
        float* __restrict__ last, float* __restrict__ cur,
        float* __restrict__ out, int out_size) {
    int b = blockIdx.x, tid = threadIdx.x;
    const float4* r4 = (const float4*)(hn + (size_t)(b * TTOT + TTOT - 1) * DIM);
    float4 v = r4[tid];
    ((float4*)(last + (size_t)b * DIM))[tid] = v;
    float4 w = ((const float4*)Weos)[tid];
    float p = v.x*w.x + v.y*w.y + v.z*w.z + v.w*w.w;
    __shared__ float red[256];
    red[tid] = p;
    __syncthreads();
    for (int s = 128; s; s >>= 1) {
        if (tid < s) red[tid] += red[tid + s];
        __syncthreads();
    }
    if (tid == 0 && (1024 + b) < out_size) {
        float e = red[0] + beos[0];
        out[1024 + b] = (e > 0.5f) ? 1.0f : 0.0f;
    }
    if (tid < LDIMC) cur[b * LDIMC + tid] = noise[b * LDIMC + tid];  // * sqrt(TEMP=1)
}

// ---------------- flow decoder ----------------
__global__ void build_inp_kernel(const float* __restrict__ last,
                                 const float* __restrict__ cur,
                                 float s, float t, float* __restrict__ inp) {
    int i = blockIdx.x * blockDim.x + threadIdx.x;
    if (i >= BDIM * KF1) return;
    int m = i / KF1, k = i - m * KF1;
    float v;
    if (k < DIM)            v = last[m * DIM + k];
    else if (k == DIM)      v = s;
    else if (k == DIM + 1)  v = t;
    else                    v = cur[m * LDIMC + (k - DIM - 2)];
    inp[i] = v;
}

// mode: 1 = silu ; 2 = accumulate into out += v/NSTEPS
__global__ void __launch_bounds__(128) flow_fc_kernel(
        const float* __restrict__ X, const float* __restrict__ W,
        const float* __restrict__ bias, float* __restrict__ out,
        int K, int N, int mode) {
    __shared__ float xs[KF1 * BDIM];   // [k][m] layout, 36928 B
    int tid = threadIdx.x;
    int n = blockIdx.x * 128 + tid;
    for (int i = tid; i < K * BDIM; i += 128) {
        int m = i / K, k = i - m * K;
        xs[k * BDIM + m] = X[i];
    }
    __syncthreads();
    float acc[8] = {0,0,0,0,0,0,0,0};
    const float* wp = W + n;
    #pragma unroll 4
    for (int k = 0; k < K; k++) {
        float w = wp[(size_t)k * N];
        float4 x0 = *(const float4*)&xs[k * 8];
        float4 x1 = *(const float4*)&xs[k * 8 + 4];
        acc[0] = fmaf(w, x0.x, acc[0]); acc[1] = fmaf(w, x0.y, acc[1]);
        acc[2] = fmaf(w, x0.z, acc[2]); acc[3] = fmaf(w, x0.w, acc[3]);
        acc[4] = fmaf(w, x1.x, acc[4]); acc[5] = fmaf(w, x1.y, acc[5]);
        acc[6] = fmaf(w, x1.z, acc[6]); acc[7] = fmaf(w, x1.w, acc[7]);
    }
    float bn = bias[n];
    #pragma unroll
    for (int m = 0; m < 8; m++) {
        float v = acc[m] + bn;
        if (mode == 1)      out[m * N + n] = silu(v);
        else                out[m * N + n] += v * (1.0f / NSTEPS);
    }
}

__global__ void writeout_kernel(const float* __restrict__ cur,
                                float* __restrict__ out, int out_size) {
    int i = blockIdx.x * blockDim.x + threadIdx.x;
    if (i >= out_size) return;
    if (i < 1024)       out[i] = cur[i];
    else if (i >= 1032) out[i] = 0.0f;   // eos slots 1024..1031 written by finalize
}

// ---------------- host orchestration ----------------
extern "C" void kernel_launch(void* const* d_in, const int* in_sizes, int n_in,
                              void* d_out, int out_size) {
    const float* seq   = (const float*)d_in[0];
    const float* text  = (const float*)d_in[1];
    const float* noise = (const float*)d_in[2];
    // d_in[3] = lsd_decode_steps (16, fixed)
    const float* bos   = (const float*)d_in[4];
    const float* W_in  = (const float*)d_in[5];
    const float* b_in  = (const float*)d_in[6];
    const float* ln1g  = (const float*)d_in[7];
    const float* ln1b  = (const float*)d_in[8];
    const float* Wqkv  = (const float*)d_in[9];
    const float* bqkv  = (const float*)d_in[10];
    const float* Wo    = (const float*)d_in[11];
    const float* bo    = (const float*)d_in[12];
    const float* ln2g  = (const float*)d_in[13];
    const float* ln2b  = (const float*)d_in[14];
    const float* W1    = (const float*)d_in[15];
    const float* b1    = (const float*)d_in[16];
    const float* W2    = (const float*)d_in[17];
    const float* b2    = (const float*)d_in[18];
    const float* ong   = (const float*)d_in[19];
    const float* onb   = (const float*)d_in[20];
    const float* Weos  = (const float*)d_in[21];
    const float* beos  = (const float*)d_in[22];
    const float* Wf1   = (const float*)d_in[23];
    const float* bf1   = (const float*)d_in[24];
    const float* Wf2   = (const float*)d_in[25];
    const float* bf2   = (const float*)d_in[26];
    const float* Wf3   = (const float*)d_in[27];
    const float* bf3   = (const float*)d_in[28];
    float* out = (float*)d_out;

    float *p_seqf, *p_x, *p_h, *p_tmp, *p_qkv, *p_att, *p_mid;
    float *p_last, *p_cur, *p_inp, *p_f1, *p_f2;
    cudaGetSymbolAddress((void**)&p_seqf, g_seqf);
    cudaGetSymbolAddress((void**)&p_x,    g_x);
    cudaGetSymbolAddress((void**)&p_h,    g_h);
    cudaGetSymbolAddress((void**)&p_tmp,  g_tmp);
    cudaGetSymbolAddress((void**)&p_qkv,  g_qkv);
    cudaGetSymbolAddress((void**)&p_att,  g_att);
    cudaGetSymbolAddress((void**)&p_mid,  g_mid);
    cudaGetSymbolAddress((void**)&p_last, g_last);
    cudaGetSymbolAddress((void**)&p_cur,  g_cur);
    cudaGetSymbolAddress((void**)&p_inp,  g_inp);
    cudaGetSymbolAddress((void**)&p_f1,   g_f1);
    cudaGetSymbolAddress((void**)&p_f2,   g_f2);

    // 1) nan-fix + input projection + concat
    int nseq = BDIM * TSEQ * LDIMC;
    nanfix_kernel<<<(nseq + 255) / 256, 256>>>(seq, bos, p_seqf, nseq);
    sgemm_kernel<<<dim3(DIM / 128, (BDIM * TSEQ) / 128), 256>>>(
        p_seqf, W_in, b_in, nullptr, p_x, BDIM * TSEQ, DIM, LDIMC, 0);
    concat_kernel<<<(MROWS * 256 + 255) / 256, 256>>>(text, p_x, p_h);

    // 2) transformer layers
    for (int l = 0; l < NLAYER; l++) {
        layernorm_kernel<<<MROWS, 256>>>(p_h, p_tmp, ln1g + l * DIM, ln1b + l * DIM);
        sgemm_kernel<<<dim3(3 * DIM / 128, MROWS / 128), 256>>>(
            p_tmp, Wqkv + (size_t)l * DIM * 3 * DIM, bqkv + l * 3 * DIM,
            nullptr, p_qkv, MROWS, 3 * DIM, DIM, 0);
        attn_kernel<<<dim3(TTOT / 64, HEADS, BDIM), 64>>>(p_qkv, p_att);
        sgemm_kernel<<<dim3(DIM / 128, MROWS / 128), 256>>>(
            p_att, Wo + (size_t)l * DIM * DIM, bo + l * DIM,
            p_h, p_h, MROWS, DIM, DIM, 2);
        layernorm_kernel<<<MROWS, 256>>>(p_h, p_tmp, ln2g + l * DIM, ln2b + l * DIM);
        sgemm_kernel<<<dim3(FFN / 128, MROWS / 128), 256>>>(
            p_tmp, W1 + (size_t)l * DIM * FFN, b1 + l * FFN,
            nullptr, p_mid, MROWS, FFN, DIM, 1);
        sgemm_kernel<<<dim3(DIM / 128, MROWS / 128), 256>>>(
            p_mid, W2 + (size_t)l * FFN * DIM, b2 + l * DIM,
            p_h, p_h, MROWS, DIM, FFN, 2);
    }

    // 3) output norm + eos + current init
    layernorm_kernel<<<MROWS, 256>>>(p_h, p_tmp, ong, onb);
    finalize_kernel<<<BDIM, 256>>>(p_tmp, noise, Weos, beos,
                                   p_last, p_cur, out, out_size);

    // 4) flow decoder: 16 sequential steps
    for (int i = 0; i < NSTEPS; i++) {
        float s = (float)i / NSTEPS;
        float t = (float)(i + 1) / NSTEPS;
        build_inp_kernel<<<(BDIM * KF1 + 127) / 128, 128>>>(p_last, p_cur, s, t, p_inp);
        flow_fc_kernel<<<HID / 128, 128>>>(p_inp, Wf1, bf1, p_f1, KF1, HID, 1);
        flow_fc_kernel<<<HID / 128, 128>>>(p_f1,  Wf2, bf2, p_f2, HID, HID, 1);
        flow_fc_kernel<<<1, 128>>>(p_f2, Wf3, bf3, p_cur, HID, LDIMC, 2);
    }

    // 5) write output
    int ncov = out_size > 1024 ? out_size : 1024;
    writeout_kernel<<<(ncov + 255) / 256, 256>>>(p_cur, out, out_size);
}

// round 2
// speedup vs baseline: 1.7244x; 1.7244x over previous
#include <cuda_runtime.h>
#include <cuda_bf16.h>
#include <math.h>
#include <stdint.h>

// ---------------- model constants ----------------
#define BDIM   8
#define TTXT   64
#define TSEQ   256
#define TTOT   320            // 64 + 256
#define MROWS  (BDIM*TTOT)    // 2560
#define DIM    1024
#define LDIMC  128
#define FFN    4096
#define HEADS  16
#define HDIM   64
#define NLAYER 4
#define HID    1024
#define KF1    (DIM + LDIMC + 2)   // 1154
#define NSTEPS 16

// ---------------- scratch (device globals; no allocations allowed) ----------------
__device__ float g_seqf[BDIM*TSEQ*LDIMC];
__device__ float g_x   [BDIM*TSEQ*DIM];
__device__ float g_h   [MROWS*DIM];
__device__ float g_tmp [MROWS*DIM];
__device__ float g_qkv [MROWS*3*DIM];
__device__ float g_att [MROWS*DIM];
__device__ float g_mid [MROWS*FFN];
__device__ float g_last[BDIM*DIM];
__device__ float g_cur [BDIM*LDIMC];
__device__ float g_f1  [BDIM*HID];
__device__ float g_f2  [BDIM*HID];

// ---------------- helpers ----------------
__device__ __forceinline__ float gelu_tanh(float x) {
    const float c = 0.7978845608028654f;
    float t = c * (x + 0.044715f * x * x * x);
    return 0.5f * x * (1.0f + tanhf(t));
}
__device__ __forceinline__ float silu(float x) {
    return x / (1.0f + __expf(-x));
}
__device__ __forceinline__ uint32_t f2tf(float x) {
    uint32_t u;
    asm("cvt.rna.tf32.f32 %0, %1;" : "=r"(u) : "f"(x));
    return u;
}
__device__ __forceinline__ void cp_async16(void* smem_dst, const void* gmem_src) {
    uint32_t s = (uint32_t)__cvta_generic_to_shared(smem_dst);
    asm volatile("cp.async.cg.shared.global [%0], [%1], 16;\n" :: "r"(s), "l"(gmem_src));
}

// ---------------- elementwise / setup kernels ----------------
__global__ void nanfix_kernel(const float* __restrict__ seq,
                              const float* __restrict__ bos,
                              float* __restrict__ out, int n) {
    int i = blockIdx.x * blockDim.x + threadIdx.x;
    if (i < n) {
        float v = seq[i];
        out[i] = (v != v) ? bos[i & (LDIMC - 1)] : v;
    }
}

__global__ void concat_kernel(const float* __restrict__ text,
                              const float* __restrict__ x,
                              float* __restrict__ h) {
    int idx = blockIdx.x * blockDim.x + threadIdx.x;
    int row = idx >> 8;
    int c4  = idx & 255;
    if (row >= MROWS) return;
    int b = row / TTOT, t = row - b * TTOT;
    float4 v;
    if (t < TTXT)
        v = ((const float4*)text)[(size_t)(b * TTXT + t) * 256 + c4];
    else
        v = ((const float4*)x)[(size_t)(b * TSEQ + (t - TTXT)) * 256 + c4];
    ((float4*)h)[(size_t)row * 256 + c4] = v;
}

// ---------------- LayerNorm ----------------
__global__ void __launch_bounds__(256) layernorm_kernel(
        const float* __restrict__ in, float* __restrict__ out,
        const float* __restrict__ g, const float* __restrict__ bta) {
    int row = blockIdx.x;
    int tid = threadIdx.x;
    const float4* in4 = (const float4*)(in + (size_t)row * DIM);
    float4 v = in4[tid];
    float s  = v.x + v.y + v.z + v.w;
    float ss = v.x*v.x + v.y*v.y + v.z*v.z + v.w*v.w;
    #pragma unroll
    for (int o = 16; o; o >>= 1) {
        s  += __shfl_xor_sync(0xffffffffu, s,  o);
        ss += __shfl_xor_sync(0xffffffffu, ss, o);
    }
    __shared__ float sh[16];
    int w = tid >> 5, l = tid & 31;
    if (l == 0) { sh[w] = s; sh[8 + w] = ss; }
    __syncthreads();
    float S = 0.f, SS = 0.f;
    #pragma unroll
    for (int i = 0; i < 8; i++) { S += sh[i]; SS += sh[8 + i]; }
    float mean = S * (1.0f / DIM);
    float var  = SS * (1.0f / DIM) - mean * mean;
    float rs   = rsqrtf(var + 1e-5f);
    float4 gg = ((const float4*)g)[tid];
    float4 bb = ((const float4*)bta)[tid];
    float4 o4;
    o4.x = (v.x - mean) * rs * gg.x + bb.x;
    o4.y = (v.y - mean) * rs * gg.y + bb.y;
    o4.z = (v.z - mean) * rs * gg.z + bb.z;
    o4.w = (v.w - mean) * rs * gg.w + bb.w;
    ((float4*)(out + (size_t)row * DIM))[tid] = o4;
}

// ---------------- TF32 tensor-core GEMM ----------------
// C = epi(A@B + bias [, res]) ; A: MxK rm, B: KxN rm. M,N mult of 128; K mult of 32.
// epi: 0 = bias ; 1 = bias+gelu ; 2 = bias+residual
#define ASTRIDE 36
#define BSTRIDE 136
#define AS_ELEMS (128*ASTRIDE)    // per stage
#define BS_ELEMS (32*BSTRIDE)
#define TG_SMEM ((2*AS_ELEMS + 2*BS_ELEMS)*4)

__global__ void __launch_bounds__(256, 2) tgemm_kernel(
        const float* __restrict__ A, const float* __restrict__ B,
        const float* __restrict__ bias, const float* __restrict__ res,
        float* __restrict__ C, int M, int N, int K, int epi) {
    extern __shared__ float sm[];
    float* As = sm;                 // [2][128][36]
    float* Bs = sm + 2 * AS_ELEMS;  // [2][32][136]

    const int tid  = threadIdx.x;
    const int bm   = blockIdx.y * 128;
    const int bn   = blockIdx.x * 128;
    const int warp = tid >> 5, lane = tid & 31;
    const int wm = (warp & 3) * 32;   // 4 warps along M
    const int wn = (warp >> 2) * 64;  // 2 warps along N
    const int g  = lane >> 2, t = lane & 3;

    const float* Abase = A + (size_t)bm * K;
    const float* Bbase = B + bn;

    // stage load
    auto loadStage = [&](int kt, int stage) {
        const float* Ag = Abase + kt * 32;
        float* Ad = As + stage * AS_ELEMS;
        #pragma unroll
        for (int i = 0; i < 4; i++) {
            int idx = tid + i * 256;
            int r = idx >> 3, c4 = idx & 7;
            cp_async16(Ad + r * ASTRIDE + c4 * 4, Ag + (size_t)r * K + c4 * 4);
        }
        const float* Bg = Bbase + (size_t)(kt * 32) * N;
        float* Bd = Bs + stage * BS_ELEMS;
        #pragma unroll
        for (int i = 0; i < 4; i++) {
            int idx = tid + i * 256;
            int r = idx >> 5, c4 = idx & 31;
            cp_async16(Bd + r * BSTRIDE + c4 * 4, Bg + (size_t)r * N + c4 * 4);
        }
        asm volatile("cp.async.commit_group;\n" ::);
    };

    float acc[2][8][4];
    #pragma unroll
    for (int i = 0; i < 2; i++)
        #pragma unroll
        for (int j = 0; j < 8; j++)
            #pragma unroll
            for (int q = 0; q < 4; q++) acc[i][j][q] = 0.f;

    const int nk = K >> 5;
    loadStage(0, 0);

    for (int kt = 0; kt < nk; kt++) {
        if (kt + 1 < nk) {
            loadStage(kt + 1, (kt + 1) & 1);
            asm volatile("cp.async.wait_group 1;\n" ::);
        } else {
            asm volatile("cp.async.wait_group 0;\n" ::);
        }
        __syncthreads();

        const float* Ab = As + (kt & 1) * AS_ELEMS;
        const float* Bb = Bs + (kt & 1) * BS_ELEMS;

        #pragma unroll
        for (int ks = 0; ks < 4; ks++) {
            const int k0 = ks * 8;
            uint32_t af[2][4], bf[8][2];
            #pragma unroll
            for (int mt = 0; mt < 2; mt++) {
                int m0 = wm + mt * 16 + g;
                af[mt][0] = f2tf(Ab[(m0)     * ASTRIDE + k0 + t]);
                af[mt][1] = f2tf(Ab[(m0 + 8) * ASTRIDE + k0 + t]);
                af[mt][2] = f2tf(Ab[(m0)     * ASTRIDE + k0 + t + 4]);
                af[mt][3] = f2tf(Ab[(m0 + 8) * ASTRIDE + k0 + t + 4]);
            }
            #pragma unroll
            for (int nt = 0; nt < 8; nt++) {
                int n0 = wn + nt * 8 + g;
                bf[nt][0] = f2tf(Bb[(k0 + t)     * BSTRIDE + n0]);
                bf[nt][1] = f2tf(Bb[(k0 + t + 4) * BSTRIDE + n0]);
            }
            #pragma unroll
            for (int mt = 0; mt < 2; mt++)
                #pragma unroll
                for (int nt = 0; nt < 8; nt++) {
                    asm volatile(
                        "mma.sync.aligned.m16n8k8.row.col.f32.tf32.tf32.f32 "
                        "{%0,%1,%2,%3}, {%4,%5,%6,%7}, {%8,%9}, {%0,%1,%2,%3};\n"
                        : "+f"(acc[mt][nt][0]), "+f"(acc[mt][nt][1]),
                          "+f"(acc[mt][nt][2]), "+f"(acc[mt][nt][3])
                        : "r"(af[mt][0]), "r"(af[mt][1]), "r"(af[mt][2]), "r"(af[mt][3]),
                          "r"(bf[nt][0]), "r"(bf[nt][1]));
                }
        }
        __syncthreads();
    }

    // epilogue
    #pragma unroll
    for (int mt = 0; mt < 2; mt++) {
        #pragma unroll
        for (int nt = 0; nt < 8; nt++) {
            int c = bn + wn + nt * 8 + t * 2;
            float bx = bias[c], by = bias[c + 1];
            #pragma unroll
            for (int rr = 0; rr < 2; rr++) {
                int gm = bm + wm + mt * 16 + g + rr * 8;
                size_t off = (size_t)gm * N + c;
                float vx = acc[mt][nt][rr * 2 + 0] + bx;
                float vy = acc[mt][nt][rr * 2 + 1] + by;
                if (epi == 1) { vx = gelu_tanh(vx); vy = gelu_tanh(vy); }
                else if (epi == 2) {
                    float2 r2 = *(const float2*)&res[off];
                    vx += r2.x; vy += r2.y;
                }
                float2 o2 = make_float2(vx, vy);
                *(float2*)&C[off] = o2;
            }
        }
    }
}

// ---------------- causal attention (fp32, flash-style) ----------------
__global__ void __launch_bounds__(64) attn_kernel(
        const float* __restrict__ qkv, float* __restrict__ o) {
    const int qt = blockIdx.x;
    const int h  = blockIdx.y;
    const int b  = blockIdx.z;
    const int tq = threadIdx.x;
    const int q  = qt * 64 + tq;

    __shared__ float Ks[32][68];
    __shared__ float Vs[32][68];
    __shared__ float Sb[64][33];

    float qreg[HDIM], acc[HDIM];
    const float* qp = qkv + (size_t)(b * TTOT + q) * (3 * DIM) + h * HDIM;
    #pragma unroll
    for (int d4 = 0; d4 < 16; d4++) {
        float4 v = ((const float4*)qp)[d4];
        qreg[4*d4+0] = v.x; qreg[4*d4+1] = v.y; qreg[4*d4+2] = v.z; qreg[4*d4+3] = v.w;
    }
    #pragma unroll
    for (int d = 0; d < HDIM; d++) acc[d] = 0.f;
    float mrun = -1e30f, lrun = 0.f;

    const int nkt = 2 * qt + 2;
    for (int kt = 0; kt < nkt; kt++) {
        {
            int r = tq & 31;
            bool isV = (tq >= 32);
            const float* p = qkv + (size_t)(b * TTOT + kt * 32 + r) * (3 * DIM)
                             + (isV ? 2 * DIM : DIM) + h * HDIM;
            float* dst = isV ? &Vs[r][0] : &Ks[r][0];
            #pragma unroll
            for (int d4 = 0; d4 < 16; d4++)
                ((float4*)dst)[d4] = ((const float4*)p)[d4];
        }
        __syncthreads();

        for (int j = 0; j < 32; j++) {
            float s = 0.f;
            #pragma unroll
            for (int d = 0; d < HDIM; d++) s = fmaf(qreg[d], Ks[j][d], s);
            s *= 0.125f;
            int kg = kt * 32 + j;
            Sb[tq][j] = (kg <= q) ? s : -1e30f;
        }
        float tmax = -1e30f;
        #pragma unroll
        for (int j = 0; j < 32; j++) tmax = fmaxf(tmax, Sb[tq][j]);
        float mnew = fmaxf(mrun, tmax);
        float corr = __expf(mrun - mnew);
        lrun *= corr;
        #pragma unroll
        for (int d = 0; d < HDIM; d++) acc[d] *= corr;
        for (int j = 0; j < 32; j++) {
            float p = __expf(Sb[tq][j] - mnew);
            lrun += p;
            #pragma unroll
            for (int d = 0; d < HDIM; d++) acc[d] = fmaf(p, Vs[j][d], acc[d]);
        }
        mrun = mnew;
        __syncthreads();
    }

    float inv = 1.0f / lrun;
    float* op = o + (size_t)(b * TTOT + q) * DIM + h * HDIM;
    #pragma unroll
    for (int d4 = 0; d4 < 16; d4++) {
        float4 v;
        v.x = acc[4*d4+0]*inv; v.y = acc[4*d4+1]*inv;
        v.z = acc[4*d4+2]*inv; v.w = acc[4*d4+3]*inv;
        ((float4*)op)[d4] = v;
    }
}

// ---------------- finalize ----------------
__global__ void __launch_bounds__(256) finalize_kernel(
        const float* __restrict__ hn, const float* __restrict__ noise,
        const float* __restrict__ Weos, const float* __restrict__ beos,
        float* __restrict__ last, float* __restrict__ cur,
        float* __restrict__ out, int out_size) {
    int b = blockIdx.x, tid = threadIdx.x;
    const float4* r4 = (const float4*)(hn + (size_t)(b * TTOT + TTOT - 1) * DIM);
    float4 v = r4[tid];
    ((float4*)(last + (size_t)b * DIM))[tid] = v;
    float4 w = ((const float4*)Weos)[tid];
    float p = v.x*w.x + v.y*w.y + v.z*w.z + v.w*w.w;
    __shared__ float red[256];
    red[tid] = p;
    __syncthreads();
    for (int s = 128; s; s >>= 1) {
        if (tid < s) red[tid] += red[tid + s];
        __syncthreads();
    }
    if (tid == 0 && (1024 + b) < out_size) {
        float e = red[0] + beos[0];
        out[1024 + b] = (e > 0.5f) ? 1.0f : 0.0f;
    }
    if (tid < LDIMC) cur[b * LDIMC + tid] = noise[b * LDIMC + tid];
}

// ---------------- flow decoder ----------------
// FC1 fused with input construction: inp = [last(1024), s, t, cur(128)]
__global__ void __launch_bounds__(128) flow_fc1_kernel(
        const float* __restrict__ last, const float* __restrict__ cur,
        float s, float t, const float* __restrict__ W,
        const float* __restrict__ bias, float* __restrict__ out) {
    __shared__ float xs[KF1 * BDIM];   // [k][m]
    int tid = threadIdx.x;
    int n = blockIdx.x * 128 + tid;
    for (int i = tid; i < KF1 * BDIM; i += 128) {
        int k = i >> 3, m = i & 7;
        float v;
        if (k < DIM)            v = last[m * DIM + k];
        else if (k == DIM)      v = s;
        else if (k == DIM + 1)  v = t;
        else                    v = cur[m * LDIMC + (k - DIM - 2)];
        xs[k * 8 + m] = v;
    }
    __syncthreads();
    float acc[8] = {0,0,0,0,0,0,0,0};
    const float* wp = W + n;
    #pragma unroll 4
    for (int k = 0; k < KF1; k++) {
        float w = wp[(size_t)k * HID];
        float4 x0 = *(const float4*)&xs[k * 8];
        float4 x1 = *(const float4*)&xs[k * 8 + 4];
        acc[0] = fmaf(w, x0.x, acc[0]); acc[1] = fmaf(w, x0.y, acc[1]);
        acc[2] = fmaf(w, x0.z, acc[2]); acc[3] = fmaf(w, x0.w, acc[3]);
        acc[4] = fmaf(w, x1.x, acc[4]); acc[5] = fmaf(w, x1.y, acc[5]);
        acc[6] = fmaf(w, x1.z, acc[6]); acc[7] = fmaf(w, x1.w, acc[7]);
    }
    float bn = bias[n];
    #pragma unroll
    for (int m = 0; m < 8; m++)
        out[m * HID + n] = silu(acc[m] + bn);
}

// mode: 1 = silu ; 2 = accumulate into out += v/NSTEPS
__global__ void __launch_bounds__(128) flow_fc_kernel(
        const float* __restrict__ X, const float* __restrict__ W,
        const float* __restrict__ bias, float* __restrict__ out,
        int K, int N, int mode) {
    __shared__ float xs[HID * BDIM];
    int tid = threadIdx.x;
    int n = blockIdx.x * 128 + tid;
    for (int i = tid; i < K * BDIM; i += 128) {
        int m = i / K, k = i - m * K;
        xs[k * BDIM + m] = X[i];
    }
    __syncthreads();
    float acc[8] = {0,0,0,0,0,0,0,0};
    const float* wp = W + n;
    #pragma unroll 4
    for (int k = 0; k < K; k++) {
        float w = wp[(size_t)k * N];
        float4 x0 = *(const float4*)&xs[k * 8];
        float4 x1 = *(const float4*)&xs[k * 8 + 4];
        acc[0] = fmaf(w, x0.x, acc[0]); acc[1] = fmaf(w, x0.y, acc[1]);
        acc[2] = fmaf(w, x0.z, acc[2]); acc[3] = fmaf(w, x0.w, acc[3]);
        acc[4] = fmaf(w, x1.x, acc[4]); acc[5] = fmaf(w, x1.y, acc[5]);
        acc[6] = fmaf(w, x1.z, acc[6]); acc[7] = fmaf(w, x1.w, acc[7]);
    }
    float bn = bias[n];
    #pragma unroll
    for (int m = 0; m < 8; m++) {
        float v = acc[m] + bn;
        if (mode == 1)      out[m * N + n] = silu(v);
        else                out[m * N + n] += v * (1.0f / NSTEPS);
    }
}

__global__ void writeout_kernel(const float* __restrict__ cur,
                                float* __restrict__ out, int out_size) {
    int i = blockIdx.x * blockDim.x + threadIdx.x;
    if (i >= out_size) return;
    if (i < 1024)       out[i] = cur[i];
    else if (i >= 1032) out[i] = 0.0f;
}

// ---------------- host orchestration ----------------
extern "C" void kernel_launch(void* const* d_in, const int* in_sizes, int n_in,
                              void* d_out, int out_size) {
    const float* seq   = (const float*)d_in[0];
    const float* text  = (const float*)d_in[1];
    const float* noise = (const float*)d_in[2];
    const float* bos   = (const float*)d_in[4];
    const float* W_in  = (const float*)d_in[5];
    const float* b_in  = (const float*)d_in[6];
    const float* ln1g  = (const float*)d_in[7];
    const float* ln1b  = (const float*)d_in[8];
    const float* Wqkv  = (const float*)d_in[9];
    const float* bqkv  = (const float*)d_in[10];
    const float* Wo    = (const float*)d_in[11];
    const float* bo    = (const float*)d_in[12];
    const float* ln2g  = (const float*)d_in[13];
    const float* ln2b  = (const float*)d_in[14];
    const float* W1    = (const float*)d_in[15];
    const float* b1    = (const float*)d_in[16];
    const float* W2    = (const float*)d_in[17];
    const float* b2    = (const float*)d_in[18];
    const float* ong   = (const float*)d_in[19];
    const float* onb   = (const float*)d_in[20];
    const float* Weos  = (const float*)d_in[21];
    const float* beos  = (const float*)d_in[22];
    const float* Wf1   = (const float*)d_in[23];
    const float* bf1   = (const float*)d_in[24];
    const float* Wf2   = (const float*)d_in[25];
    const float* bf2   = (const float*)d_in[26];
    const float* Wf3   = (const float*)d_in[27];
    const float* bf3   = (const float*)d_in[28];
    float* out = (float*)d_out;

    float *p_seqf, *p_x, *p_h, *p_tmp, *p_qkv, *p_att, *p_mid;
    float *p_last, *p_cur, *p_f1, *p_f2;
    cudaGetSymbolAddress((void**)&p_seqf, g_seqf);
    cudaGetSymbolAddress((void**)&p_x,    g_x);
    cudaGetSymbolAddress((void**)&p_h,    g_h);
    cudaGetSymbolAddress((void**)&p_tmp,  g_tmp);
    cudaGetSymbolAddress((void**)&p_qkv,  g_qkv);
    cudaGetSymbolAddress((void**)&p_att,  g_att);
    cudaGetSymbolAddress((void**)&p_mid,  g_mid);
    cudaGetSymbolAddress((void**)&p_last, g_last);
    cudaGetSymbolAddress((void**)&p_cur,  g_cur);
    cudaGetSymbolAddress((void**)&p_f1,   g_f1);
    cudaGetSymbolAddress((void**)&p_f2,   g_f2);

    static bool attr_set = false;
    (void)attr_set;
    cudaFuncSetAttribute(tgemm_kernel,
                         cudaFuncAttributeMaxDynamicSharedMemorySize, TG_SMEM);

    // 1) nan-fix + input projection + concat
    int nseq = BDIM * TSEQ * LDIMC;
    nanfix_kernel<<<(nseq + 255) / 256, 256>>>(seq, bos, p_seqf, nseq);
    tgemm_kernel<<<dim3(DIM / 128, (BDIM * TSEQ) / 128), 256, TG_SMEM>>>(
        p_seqf, W_in, b_in, nullptr, p_x, BDIM * TSEQ, DIM, LDIMC, 0);
    concat_kernel<<<(MROWS * 256 + 255) / 256, 256>>>(text, p_x, p_h);

    // 2) transformer layers
    for (int l = 0; l < NLAYER; l++) {
        layernorm_kernel<<<MROWS, 256>>>(p_h, p_tmp, ln1g + l * DIM, ln1b + l * DIM);
        tgemm_kernel<<<dim3(3 * DIM / 128, MROWS / 128), 256, TG_SMEM>>>(
            p_tmp, Wqkv + (size_t)l * DIM * 3 * DIM, bqkv + l * 3 * DIM,
            nullptr, p_qkv, MROWS, 3 * DIM, DIM, 0);
        attn_kernel<<<dim3(TTOT / 64, HEADS, BDIM), 64>>>(p_qkv, p_att);
        tgemm_kernel<<<dim3(DIM / 128, MROWS / 128), 256, TG_SMEM>>>(
            p_att, Wo + (size_t)l * DIM * DIM, bo + l * DIM,
            p_h, p_h, MROWS, DIM, DIM, 2);
        layernorm_kernel<<<MROWS, 256>>>(p_h, p_tmp, ln2g + l * DIM, ln2b + l * DIM);
        tgemm_kernel<<<dim3(FFN / 128, MROWS / 128), 256, TG_SMEM>>>(
            p_tmp, W1 + (size_t)l * DIM * FFN, b1 + l * FFN,
            nullptr, p_mid, MROWS, FFN, DIM, 1);
        tgemm_kernel<<<dim3(DIM / 128, MROWS / 128), 256, TG_SMEM>>>(
            p_mid, W2 + (size_t)l * FFN * DIM, b2 + l * DIM,
            p_h, p_h, MROWS, DIM, FFN, 2);
    }

    // 3) output norm + eos + current init
    layernorm_kernel<<<MROWS, 256>>>(p_h, p_tmp, ong, onb);
    finalize_kernel<<<BDIM, 256>>>(p_tmp, noise, Weos, beos,
                                   p_last, p_cur, out, out_size);

    // 4) flow decoder
    for (int i = 0; i < NSTEPS; i++) {
        float s = (float)i / NSTEPS;
        float t = (float)(i + 1) / NSTEPS;
        flow_fc1_kernel<<<HID / 128, 128>>>(p_last, p_cur, s, t, Wf1, bf1, p_f1);
        flow_fc_kernel<<<HID / 128, 128>>>(p_f1, Wf2, bf2, p_f2, HID, HID, 1);
        flow_fc_kernel<<<1, 128>>>(p_f2, Wf3, bf3, p_cur, HID, LDIMC, 2);
    }

    // 5) write output
    int ncov = out_size > 1024 ? out_size : 1024;
    writeout_kernel<<<(ncov + 255) / 256, 256>>>(p_cur, out, out_size);
}

// round 3
// speedup vs baseline: 3.3101x; 1.9195x over previous
#include <cuda_runtime.h>
#include <cuda_bf16.h>
#include <math.h>
#include <stdint.h>

// ---------------- model constants ----------------
#define BDIM   8
#define TTXT   64
#define TSEQ   256
#define TTOT   320
#define MROWS  (BDIM*TTOT)    // 2560
#define DIM    1024
#define LDIMC  128
#define FFN    4096
#define HEADS  16
#define HDIM   64
#define NLAYER 4
#define HID    1024
#define KF1    1154
#define KP1    1160           // padded, %4==0
#define NSTEPS 16

// ---------------- scratch ----------------
__device__ float g_seqf[BDIM*TSEQ*LDIMC];
__device__ float g_x   [BDIM*TSEQ*DIM];
__device__ float g_h   [MROWS*DIM];
__device__ float g_tmp [MROWS*DIM];
__device__ float g_qkv [MROWS*3*DIM];
__device__ float g_att [MROWS*DIM];
__device__ float g_mid [MROWS*FFN];
__device__ float g_last[BDIM*DIM];
__device__ float g_cur [BDIM*LDIMC];
__device__ float g_f1  [BDIM*HID];
__device__ float g_f2  [BDIM*HID];
__device__ float g_p01 [2*MROWS*DIM];          // split-K partials
// rounded weights
__device__ float g_win [LDIMC*DIM];
__device__ float g_wqkv[NLAYER*DIM*3*DIM];
__device__ float g_wo  [NLAYER*DIM*DIM];
__device__ float g_w1  [NLAYER*DIM*FFN];
__device__ float g_w2  [NLAYER*FFN*DIM];
// transposed flow weights
__device__ float g_wf1t[HID*KP1];
__device__ float g_wf2t[HID*HID];
__device__ float g_wf3t[LDIMC*HID];

// ---------------- helpers ----------------
__device__ __forceinline__ float gelu_tanh(float x) {
    const float c = 0.7978845608028654f;
    float t = c * (x + 0.044715f * x * x * x);
    return 0.5f * x * (1.0f + tanhf(t));
}
__device__ __forceinline__ float silu(float x) { return x / (1.0f + __expf(-x)); }
__device__ __forceinline__ float rna_tf32(float x) {
    uint32_t u;
    asm("cvt.rna.tf32.f32 %0, %1;" : "=r"(u) : "f"(x));
    return __uint_as_float(u);
}
__device__ __forceinline__ void cp_async16(void* smem_dst, const void* gmem_src) {
    uint32_t s = (uint32_t)__cvta_generic_to_shared(smem_dst);
    asm volatile("cp.async.cg.shared.global [%0], [%1], 16;\n" :: "r"(s), "l"(gmem_src));
}
// smem column swizzle for attention tiles: insert 1 pad word per 16
__device__ __forceinline__ int swz(int c) { return c + (c >> 4); }

// ---------------- prep kernels ----------------
__global__ void round4_kernel(const float4* __restrict__ src,
                              float4* __restrict__ dst, int n4) {
    int i = blockIdx.x * blockDim.x + threadIdx.x;
    if (i >= n4) return;
    float4 v = src[i];
    v.x = rna_tf32(v.x); v.y = rna_tf32(v.y);
    v.z = rna_tf32(v.z); v.w = rna_tf32(v.w);
    dst[i] = v;
}
__global__ void zero_kernel(float* __restrict__ p, int n) {
    int i = blockIdx.x * blockDim.x + threadIdx.x;
    if (i < n) p[i] = 0.f;
}
// dst[c*dstride + r] = src[r*C + c]
__global__ void transpose_kernel(const float* __restrict__ src, float* __restrict__ dst,
                                 int R, int C, int dstride) {
    __shared__ float tile[32][33];
    int c0 = blockIdx.x * 32, r0 = blockIdx.y * 32;
    int tx = threadIdx.x, ty = threadIdx.y;
    #pragma unroll
    for (int i = 0; i < 4; i++) {
        int rr = r0 + ty + i * 8, cc = c0 + tx;
        if (rr < R && cc < C) tile[ty + i * 8][tx] = src[(size_t)rr * C + cc];
    }
    __syncthreads();
    #pragma unroll
    for (int i = 0; i < 4; i++) {
        int cc = c0 + ty + i * 8, rr = r0 + tx;
        if (cc < C && rr < R) dst[(size_t)cc * dstride + rr] = tile[tx][ty + i * 8];
    }
}

__global__ void nanfix_kernel(const float* __restrict__ seq,
                              const float* __restrict__ bos,
                              float* __restrict__ out, int n) {
    int i = blockIdx.x * blockDim.x + threadIdx.x;
    if (i < n) {
        float v = seq[i];
        v = (v != v) ? bos[i & (LDIMC - 1)] : v;
        out[i] = rna_tf32(v);
    }
}

__global__ void concat_kernel(const float* __restrict__ text,
                              const float* __restrict__ x,
                              float* __restrict__ h) {
    int idx = blockIdx.x * blockDim.x + threadIdx.x;
    int row = idx >> 8, c4 = idx & 255;
    if (row >= MROWS) return;
    int b = row / TTOT, t = row - b * TTOT;
    float4 v;
    if (t < TTXT)
        v = ((const float4*)text)[(size_t)(b * TTXT + t) * 256 + c4];
    else
        v = ((const float4*)x)[(size_t)(b * TSEQ + (t - TTXT)) * 256 + c4];
    ((float4*)h)[(size_t)row * 256 + c4] = v;
}

// ---------------- LayerNorm ----------------
__global__ void __launch_bounds__(256) layernorm_kernel(
        const float* __restrict__ in, float* __restrict__ out,
        const float* __restrict__ g, const float* __restrict__ bta, int round) {
    int row = blockIdx.x, tid = threadIdx.x;
    const float4* in4 = (const float4*)(in + (size_t)row * DIM);
    float4 v = in4[tid];
    float s  = v.x + v.y + v.z + v.w;
    float ss = v.x*v.x + v.y*v.y + v.z*v.z + v.w*v.w;
    #pragma unroll
    for (int o = 16; o; o >>= 1) {
        s  += __shfl_xor_sync(0xffffffffu, s,  o);
        ss += __shfl_xor_sync(0xffffffffu, ss, o);
    }
    __shared__ float sh[16];
    int w = tid >> 5, l = tid & 31;
    if (l == 0) { sh[w] = s; sh[8 + w] = ss; }
    __syncthreads();
    float S = 0.f, SS = 0.f;
    #pragma unroll
    for (int i = 0; i < 8; i++) { S += sh[i]; SS += sh[8 + i]; }
    float mean = S * (1.0f / DIM);
    float var  = SS * (1.0f / DIM) - mean * mean;
    float rs   = rsqrtf(var + 1e-5f);
    float4 gg = ((const float4*)g)[tid];
    float4 bb = ((const float4*)bta)[tid];
    float4 o4;
    o4.x = (v.x - mean) * rs * gg.x + bb.x;
    o4.y = (v.y - mean) * rs * gg.y + bb.y;
    o4.z = (v.z - mean) * rs * gg.z + bb.z;
    o4.w = (v.w - mean) * rs * gg.w + bb.w;
    if (round) {
        o4.x = rna_tf32(o4.x); o4.y = rna_tf32(o4.y);
        o4.z = rna_tf32(o4.z); o4.w = rna_tf32(o4.w);
    }
    ((float4*)(out + (size_t)row * DIM))[tid] = o4;
}

// ---------------- TF32 tensor-core GEMM (inputs pre-rounded to tf32) ----------------
// epi: 0 = bias ; 1 = bias+gelu(round) ; 2 = bias+residual ; 3 = raw partial store
#define ASTRIDE 36
#define BSTRIDE 136
#define AS_ELEMS (128*ASTRIDE)
#define BS_ELEMS (32*BSTRIDE)
#define TG_SMEM ((2*AS_ELEMS + 2*BS_ELEMS)*4)

__global__ void __launch_bounds__(256, 2) tgemm_kernel(
        const float* __restrict__ A, int lda, const float* __restrict__ B,
        const float* __restrict__ bias, const float* __restrict__ res,
        float* __restrict__ C, int M, int N, int K, int epi) {
    extern __shared__ float sm[];
    float* As = sm;
    float* Bs = sm + 2 * AS_ELEMS;

    const int tid  = threadIdx.x;
    const int bm   = blockIdx.y * 128;
    const int bn   = blockIdx.x * 128;
    const int slice = blockIdx.z;
    const int warp = tid >> 5, lane = tid & 31;
    const int wm = (warp & 3) * 32;
    const int wn = (warp >> 2) * 64;
    const int g  = lane >> 2, t = lane & 3;

    const float* Abase = A + (size_t)bm * lda + (size_t)slice * K;
    const float* Bbase = B + (size_t)slice * K * N + bn;

    auto loadStage = [&](int kt, int stage) {
        const float* Ag = Abase + kt * 32;
        float* Ad = As + stage * AS_ELEMS;
        #pragma unroll
        for (int i = 0; i < 4; i++) {
            int idx = tid + i * 256;
            int r = idx >> 3, c4 = idx & 7;
            cp_async16(Ad + r * ASTRIDE + c4 * 4, Ag + (size_t)r * lda + c4 * 4);
        }
        const float* Bg = Bbase + (size_t)(kt * 32) * N;
        float* Bd = Bs + stage * BS_ELEMS;
        #pragma unroll
        for (int i = 0; i < 4; i++) {
            int idx = tid + i * 256;
            int r = idx >> 5, c4 = idx & 31;
            cp_async16(Bd + r * BSTRIDE + c4 * 4, Bg + (size_t)r * N + c4 * 4);
        }
        asm volatile("cp.async.commit_group;\n" ::);
    };

    float acc[2][8][4];
    #pragma unroll
    for (int i = 0; i < 2; i++)
        #pragma unroll
        for (int j = 0; j < 8; j++)
            #pragma unroll
            for (int q = 0; q < 4; q++) acc[i][j][q] = 0.f;

    const int nk = K >> 5;
    loadStage(0, 0);

    for (int kt = 0; kt < nk; kt++) {
        if (kt + 1 < nk) {
            loadStage(kt + 1, (kt + 1) & 1);
            asm volatile("cp.async.wait_group 1;\n" ::);
        } else {
            asm volatile("cp.async.wait_group 0;\n" ::);
        }
        __syncthreads();

        const float* Ab = As + (kt & 1) * AS_ELEMS;
        const float* Bb = Bs + (kt & 1) * BS_ELEMS;

        #pragma unroll
        for (int ks = 0; ks < 4; ks++) {
            const int k0 = ks * 8;
            uint32_t af[2][4], bf[8][2];
            #pragma unroll
            for (int mt = 0; mt < 2; mt++) {
                int m0 = wm + mt * 16 + g;
                af[mt][0] = __float_as_uint(Ab[(m0)     * ASTRIDE + k0 + t]);
                af[mt][1] = __float_as_uint(Ab[(m0 + 8) * ASTRIDE + k0 + t]);
                af[mt][2] = __float_as_uint(Ab[(m0)     * ASTRIDE + k0 + t + 4]);
                af[mt][3] = __float_as_uint(Ab[(m0 + 8) * ASTRIDE + k0 + t + 4]);
            }
            #pragma unroll
            for (int nt = 0; nt < 8; nt++) {
                int n0 = wn + nt * 8 + g;
                bf[nt][0] = __float_as_uint(Bb[(k0 + t)     * BSTRIDE + n0]);
                bf[nt][1] = __float_as_uint(Bb[(k0 + t + 4) * BSTRIDE + n0]);
            }
            #pragma unroll
            for (int mt = 0; mt < 2; mt++)
                #pragma unroll
                for (int nt = 0; nt < 8; nt++) {
                    asm volatile(
                        "mma.sync.aligned.m16n8k8.row.col.f32.tf32.tf32.f32 "
                        "{%0,%1,%2,%3}, {%4,%5,%6,%7}, {%8,%9}, {%0,%1,%2,%3};\n"
                        : "+f"(acc[mt][nt][0]), "+f"(acc[mt][nt][1]),
                          "+f"(acc[mt][nt][2]), "+f"(acc[mt][nt][3])
                        : "r"(af[mt][0]), "r"(af[mt][1]), "r"(af[mt][2]), "r"(af[mt][3]),
                          "r"(bf[nt][0]), "r"(bf[nt][1]));
                }
        }
        __syncthreads();
    }

    float* Cout = (epi == 3) ? (C + (size_t)slice * M * N) : C;
    #pragma unroll
    for (int mt = 0; mt < 2; mt++) {
        #pragma unroll
        for (int nt = 0; nt < 8; nt++) {
            int c = bn + wn + nt * 8 + t * 2;
            float bx = 0.f, by = 0.f;
            if (epi != 3) { bx = bias[c]; by = bias[c + 1]; }
            #pragma unroll
            for (int rr = 0; rr < 2; rr++) {
                int gm = bm + wm + mt * 16 + g + rr * 8;
                size_t off = (size_t)gm * N + c;
                float vx = acc[mt][nt][rr * 2 + 0] + bx;
                float vy = acc[mt][nt][rr * 2 + 1] + by;
                if (epi == 1) {
                    vx = rna_tf32(gelu_tanh(vx)); vy = rna_tf32(gelu_tanh(vy));
                } else if (epi == 2) {
                    float2 r2 = *(const float2*)&res[off];
                    vx += r2.x; vy += r2.y;
                }
                *(float2*)&Cout[off] = make_float2(vx, vy);
            }
        }
    }
}

// split-K combine (N=1024): h += p0 + p1 + bias
__global__ void __launch_bounds__(256) combine2_kernel(
        const float* __restrict__ p0, const float* __restrict__ p1,
        const float* __restrict__ bias, float* __restrict__ h) {
    int i = blockIdx.x * blockDim.x + threadIdx.x;   // float4 index
    if (i >= MROWS * DIM / 4) return;
    float4 a = ((const float4*)p0)[i];
    float4 b = ((const float4*)p1)[i];
    float4 r = ((const float4*)h)[i];
    float4 bb = *(const float4*)&bias[(i & 255) << 2];
    r.x += a.x + b.x + bb.x;
    r.y += a.y + b.y + bb.y;
    r.z += a.z + b.z + bb.z;
    r.w += a.w + b.w + bb.w;
    ((float4*)h)[i] = r;
}

// ---------------- causal attention: 256 thr, 4 threads/query ----------------
__global__ void __launch_bounds__(256) attn_kernel(
        const float* __restrict__ qkv, float* __restrict__ o) {
    const int qt = blockIdx.x, hh = blockIdx.y, b = blockIdx.z;
    const int tid = threadIdx.x;
    const int ql = tid >> 2, part = tid & 3;
    const int q  = qt * 64 + ql;

    __shared__ float Ks[64 * 68];
    __shared__ float Vs[64 * 68];

    float qreg[16], acc[16];
    const float* qp = qkv + (size_t)(b * TTOT + q) * (3 * DIM) + hh * HDIM + part * 16;
    #pragma unroll
    for (int i = 0; i < 4; i++) {
        float4 v = ((const float4*)qp)[i];
        qreg[4*i+0] = v.x; qreg[4*i+1] = v.y; qreg[4*i+2] = v.z; qreg[4*i+3] = v.w;
    }
    #pragma unroll
    for (int d = 0; d < 16; d++) acc[d] = 0.f;
    float mrun = -1e30f, lrun = 0.f;

    const int nkt = qt + 1;
    for (int kt = 0; kt < nkt; kt++) {
        {
            int r = tid >> 2, c = (tid & 3) * 16;
            const float* kp = qkv + (size_t)(b * TTOT + kt * 64 + r) * (3 * DIM)
                              + DIM + hh * HDIM + c;
            const float* vp = kp + DIM;
            #pragma unroll
            for (int i = 0; i < 4; i++) {
                float4 kv = ((const float4*)kp)[i];
                float4 vv = ((const float4*)vp)[i];
                int cb = c + i * 4;
                Ks[r * 68 + swz(cb+0)] = kv.x; Ks[r * 68 + swz(cb+1)] = kv.y;
                Ks[r * 68 + swz(cb+2)] = kv.z; Ks[r * 68 + swz(cb+3)] = kv.w;
                Vs[r * 68 + swz(cb+0)] = vv.x; Vs[r * 68 + swz(cb+1)] = vv.y;
                Vs[r * 68 + swz(cb+2)] = vv.z; Vs[r * 68 + swz(cb+3)] = vv.w;
            }
        }
        __syncthreads();

        const int pbase = part * 17;   // swz(part*16) = part*16 + part
        for (int j = 0; j < 64; j++) {
            const float* kr = &Ks[j * 68 + pbase];
            float s = 0.f;
            #pragma unroll
            for (int d = 0; d < 16; d++) s = fmaf(qreg[d], kr[d], s);
            s += __shfl_xor_sync(0xffffffffu, s, 1);
            s += __shfl_xor_sync(0xffffffffu, s, 2);
            s *= 0.125f;
            int kg = kt * 64 + j;
            s = (kg <= q) ? s : -1e30f;
            if (s > mrun) {
                float corr = __expf(mrun - s);
                lrun *= corr;
                #pragma unroll
                for (int d = 0; d < 16; d++) acc[d] *= corr;
                mrun = s;
            }
            float p = __expf(s - mrun);
            lrun += p;
            const float* vr = &Vs[j * 68 + pbase];
            #pragma unroll
            for (int d = 0; d < 16; d++) acc[d] = fmaf(p, vr[d], acc[d]);
        }
        __syncthreads();
    }

    float inv = 1.0f / lrun;
    float* op = o + (size_t)(b * TTOT + q) * DIM + hh * HDIM + part * 16;
    #pragma unroll
    for (int i = 0; i < 4; i++) {
        float4 v;
        v.x = rna_tf32(acc[4*i+0] * inv); v.y = rna_tf32(acc[4*i+1] * inv);
        v.z = rna_tf32(acc[4*i+2] * inv); v.w = rna_tf32(acc[4*i+3] * inv);
        ((float4*)op)[i] = v;
    }
}

// ---------------- finalize ----------------
__global__ void __launch_bounds__(256) finalize_kernel(
        const float* __restrict__ hn, const float* __restrict__ noise,
        const float* __restrict__ Weos, const float* __restrict__ beos,
        float* __restrict__ last, float* __restrict__ cur,
        float* __restrict__ out, int out_size) {
    int b = blockIdx.x, tid = threadIdx.x;
    const float4* r4 = (const float4*)(hn + (size_t)(b * TTOT + TTOT - 1) * DIM);
    float4 v = r4[tid];
    ((float4*)(last + (size_t)b * DIM))[tid] = v;
    float4 w = ((const float4*)Weos)[tid];
    float p = v.x*w.x + v.y*w.y + v.z*w.z + v.w*w.w;
    __shared__ float red[256];
    red[tid] = p;
    __syncthreads();
    for (int s = 128; s; s >>= 1) {
        if (tid < s) red[tid] += red[tid + s];
        __syncthreads();
    }
    if (tid == 0 && (1024 + b) < out_size) {
        float e = red[0] + beos[0];
        out[1024 + b] = (e > 0.5f) ? 1.0f : 0.0f;
    }
    if (tid < LDIMC) cur[b * LDIMC + tid] = noise[b * LDIMC + tid];
}

// ---------------- flow decoder (transposed weights, warp per output) ----------------
__global__ void __launch_bounds__(256) flow_fc1t_kernel(
        const float* __restrict__ last, const float* __restrict__ cur,
        float s, float t, const float* __restrict__ Wt,
        const float* __restrict__ bias, float* __restrict__ out) {
    __shared__ float xs[8 * KP1];
    int tid = threadIdx.x;
    for (int i = tid; i < 8 * KP1; i += 256) {
        int m = i / KP1, k = i - m * KP1;
        float v;
        if (k < DIM)            v = last[m * DIM + k];
        else if (k == DIM)      v = s;
        else if (k == DIM + 1)  v = t;
        else if (k < KF1)       v = cur[m * LDIMC + (k - DIM - 2)];
        else                    v = 0.f;
        xs[i] = v;
    }
    __syncthreads();
    int warp = tid >> 5, lane = tid & 31;
    int n = blockIdx.x * 8 + warp;
    const float* wp = Wt + (size_t)n * KP1;
    float acc[8] = {0,0,0,0,0,0,0,0};
    for (int k0 = lane * 4; k0 < KP1; k0 += 128) {
        float4 w4 = *(const float4*)&wp[k0];
        #pragma unroll
        for (int m = 0; m < 8; m++) {
            float4 x4 = *(const float4*)&xs[m * KP1 + k0];
            acc[m] += w4.x*x4.x + w4.y*x4.y + w4.z*x4.z + w4.w*x4.w;
        }
    }
    #pragma unroll
    for (int m = 0; m < 8; m++) {
        float v = acc[m];
        #pragma unroll
        for (int o2 = 16; o2; o2 >>= 1) v += __shfl_xor_sync(0xffffffffu, v, o2);
        acc[m] = v;
    }
    if (lane == 0) {
        float bn = bias[n];
        #pragma unroll
        for (int m = 0; m < 8; m++) out[m * HID + n] = silu(acc[m] + bn);
    }
}

// mode 1: out = silu(.) ; mode 2: out += ./NSTEPS  (K=1024 exact)
__global__ void __launch_bounds__(256) flow_fct_kernel(
        const float* __restrict__ X, const float* __restrict__ Wt,
        const float* __restrict__ bias, float* __restrict__ out,
        int N, int mode) {
    __shared__ float xs[8 * HID];
    int tid = threadIdx.x;
    for (int i = tid * 4; i < 8 * HID; i += 1024)
        *(float4*)&xs[i] = *(const float4*)&X[i];
    __syncthreads();
    int warp = tid >> 5, lane = tid & 31;
    int n = blockIdx.x * 8 + warp;
    const float* wp = Wt + (size_t)n * HID;
    float acc[8] = {0,0,0,0,0,0,0,0};
    for (int k0 = lane * 4; k0 < HID; k0 += 128) {
        float4 w4 = *(const float4*)&wp[k0];
        #pragma unroll
        for (int m = 0; m < 8; m++) {
            float4 x4 = *(const float4*)&xs[m * HID + k0];
            acc[m] += w4.x*x4.x + w4.y*x4.y + w4.z*x4.z + w4.w*x4.w;
        }
    }
    #pragma unroll
    for (int m = 0; m < 8; m++) {
        float v = acc[m];
        #pragma unroll
        for (int o2 = 16; o2; o2 >>= 1) v += __shfl_xor_sync(0xffffffffu, v, o2);
        acc[m] = v;
    }
    if (lane == 0) {
        float bn = bias[n];
        #pragma unroll
        for (int m = 0; m < 8; m++) {
            float v = acc[m] + bn;
            if (mode == 1) out[m * N + n] = silu(v);
            else           out[m * N + n] += v * (1.0f / NSTEPS);
        }
    }
}

__global__ void writeout_kernel(const float* __restrict__ cur,
                                float* __restrict__ out, int out_size) {
    int i = blockIdx.x * blockDim.x + threadIdx.x;
    if (i >= out_size) return;
    if (i < 1024)       out[i] = cur[i];
    else if (i >= 1032) out[i] = 0.0f;
}

// ---------------- host orchestration ----------------
extern "C" void kernel_launch(void* const* d_in, const int* in_sizes, int n_in,
                              void* d_out, int out_size) {
    const float* seq   = (const float*)d_in[0];
    const float* text  = (const float*)d_in[1];
    const float* noise = (const float*)d_in[2];
    const float* bos   = (const float*)d_in[4];
    const float* W_in  = (const float*)d_in[5];
    const float* b_in  = (const float*)d_in[6];
    const float* ln1g  = (const float*)d_in[7];
    const float* ln1b  = (const float*)d_in[8];
    const float* Wqkv  = (const float*)d_in[9];
    const float* bqkv  = (const float*)d_in[10];
    const float* Wo    = (const float*)d_in[11];
    const float* bo    = (const float*)d_in[12];
    const float* ln2g  = (const float*)d_in[13];
    const float* ln2b  = (const float*)d_in[14];
    const float* W1    = (const float*)d_in[15];
    const float* b1    = (const float*)d_in[16];
    const float* W2    = (const float*)d_in[17];
    const float* b2    = (const float*)d_in[18];
    const float* ong   = (const float*)d_in[19];
    const float* onb   = (const float*)d_in[20];
    const float* Weos  = (const float*)d_in[21];
    const float* beos  = (const float*)d_in[22];
    const float* Wf1   = (const float*)d_in[23];
    const float* bf1   = (const float*)d_in[24];
    const float* Wf2   = (const float*)d_in[25];
    const float* bf2   = (const float*)d_in[26];
    const float* Wf3   = (const float*)d_in[27];
    const float* bf3   = (const float*)d_in[28];
    float* out = (float*)d_out;

    float *p_seqf,*p_x,*p_h,*p_tmp,*p_qkv,*p_att,*p_mid,*p_last,*p_cur,*p_f1,*p_f2,*p_p01;
    float *p_win,*p_wqkv,*p_wo,*p_w1,*p_w2,*p_wf1t,*p_wf2t,*p_wf3t;
    cudaGetSymbolAddress((void**)&p_seqf, g_seqf);
    cudaGetSymbolAddress((void**)&p_x,    g_x);
    cudaGetSymbolAddress((void**)&p_h,    g_h);
    cudaGetSymbolAddress((void**)&p_tmp,  g_tmp);
    cudaGetSymbolAddress((void**)&p_qkv,  g_qkv);
    cudaGetSymbolAddress((void**)&p_att,  g_att);
    cudaGetSymbolAddress((void**)&p_mid,  g_mid);
    cudaGetSymbolAddress((void**)&p_last, g_last);
    cudaGetSymbolAddress((void**)&p_cur,  g_cur);
    cudaGetSymbolAddress((void**)&p_f1,   g_f1);
    cudaGetSymbolAddress((void**)&p_f2,   g_f2);
    cudaGetSymbolAddress((void**)&p_p01,  g_p01);
    cudaGetSymbolAddress((void**)&p_win,  g_win);
    cudaGetSymbolAddress((void**)&p_wqkv, g_wqkv);
    cudaGetSymbolAddress((void**)&p_wo,   g_wo);
    cudaGetSymbolAddress((void**)&p_w1,   g_w1);
    cudaGetSymbolAddress((void**)&p_w2,   g_w2);
    cudaGetSymbolAddress((void**)&p_wf1t, g_wf1t);
    cudaGetSymbolAddress((void**)&p_wf2t, g_wf2t);
    cudaGetSymbolAddress((void**)&p_wf3t, g_wf3t);

    cudaFuncSetAttribute(tgemm_kernel,
                         cudaFuncAttributeMaxDynamicSharedMemorySize, TG_SMEM);

    // 0) weight prep: round to tf32, transpose flow weights
    auto rnd = [&](const float* s, float* d, size_t n) {
        round4_kernel<<<(int)((n/4 + 255)/256), 256>>>((const float4*)s, (float4*)d, (int)(n/4));
    };
    rnd(W_in, p_win, (size_t)LDIMC*DIM);
    rnd(Wqkv, p_wqkv, (size_t)NLAYER*DIM*3*DIM);
    rnd(Wo,   p_wo,   (size_t)NLAYER*DIM*DIM);
    rnd(W1,   p_w1,   (size_t)NLAYER*DIM*FFN);
    rnd(W2,   p_w2,   (size_t)NLAYER*FFN*DIM);
    zero_kernel<<<(HID*KP1 + 255)/256, 256>>>(p_wf1t, HID*KP1);
    transpose_kernel<<<dim3((HID+31)/32, (KF1+31)/32), dim3(32,8)>>>(Wf1, p_wf1t, KF1, HID, KP1);
    transpose_kernel<<<dim3((HID+31)/32, (HID+31)/32), dim3(32,8)>>>(Wf2, p_wf2t, HID, HID, HID);
    transpose_kernel<<<dim3((LDIMC+31)/32, (HID+31)/32), dim3(32,8)>>>(Wf3, p_wf3t, HID, LDIMC, HID);

    // 1) input path
    int nseq = BDIM * TSEQ * LDIMC;
    nanfix_kernel<<<(nseq + 255) / 256, 256>>>(seq, bos, p_seqf, nseq);
    tgemm_kernel<<<dim3(DIM/128, (BDIM*TSEQ)/128, 1), 256, TG_SMEM>>>(
        p_seqf, LDIMC, p_win, b_in, nullptr, p_x, BDIM*TSEQ, DIM, LDIMC, 0);
    concat_kernel<<<(MROWS * 256 + 255) / 256, 256>>>(text, p_x, p_h);

    // 2) transformer layers
    for (int l = 0; l < NLAYER; l++) {
        layernorm_kernel<<<MROWS, 256>>>(p_h, p_tmp, ln1g + l*DIM, ln1b + l*DIM, 1);
        tgemm_kernel<<<dim3(3*DIM/128, MROWS/128, 1), 256, TG_SMEM>>>(
            p_tmp, DIM, p_wqkv + (size_t)l*DIM*3*DIM, bqkv + l*3*DIM,
            nullptr, p_qkv, MROWS, 3*DIM, DIM, 0);
        attn_kernel<<<dim3(TTOT/64, HEADS, BDIM), 256>>>(p_qkv, p_att);
        // Wo: split-K=2 (klen 512)
        tgemm_kernel<<<dim3(DIM/128, MROWS/128, 2), 256, TG_SMEM>>>(
            p_att, DIM, p_wo + (size_t)l*DIM*DIM, nullptr,
            nullptr, p_p01, MROWS, DIM, 512, 3);
        combine2_kernel<<<(MROWS*DIM/4 + 255)/256, 256>>>(
            p_p01, p_p01 + (size_t)MROWS*DIM, bo + l*DIM, p_h);
        layernorm_kernel<<<MROWS, 256>>>(p_h, p_tmp, ln2g + l*DIM, ln2b + l*DIM, 1);
        tgemm_kernel<<<dim3(FFN/128, MROWS/128, 1), 256, TG_SMEM>>>(
            p_tmp, DIM, p_w1 + (size_t)l*DIM*FFN, b1 + l*FFN,
            nullptr, p_mid, MROWS, FFN, DIM, 1);
        // W2: split-K=2 (klen 2048)
        tgemm_kernel<<<dim3(DIM/128, MROWS/128, 2), 256, TG_SMEM>>>(
            p_mid, FFN, p_w2 + (size_t)l*FFN*DIM, nullptr,
            nullptr, p_p01, MROWS, DIM, 2048, 3);
        combine2_kernel<<<(MROWS*DIM/4 + 255)/256, 256>>>(
            p_p01, p_p01 + (size_t)MROWS*DIM, b2 + l*DIM, p_h);
    }

    // 3) output norm + eos + current init
    layernorm_kernel<<<MROWS, 256>>>(p_h, p_tmp, ong, onb, 0);
    finalize_kernel<<<BDIM, 256>>>(p_tmp, noise, Weos, beos, p_last, p_cur, out, out_size);

    // 4) flow decoder
    for (int i = 0; i < NSTEPS; i++) {
        float s = (float)i / NSTEPS;
        float t = (float)(i + 1) / NSTEPS;
        flow_fc1t_kernel<<<HID/8, 256>>>(p_last, p_cur, s, t, p_wf1t, bf1, p_f1);
        flow_fct_kernel<<<HID/8, 256>>>(p_f1, p_wf2t, bf2, p_f2, HID, 1);
        flow_fct_kernel<<<LDIMC/8, 256>>>(p_f2, p_wf3t, bf3, p_cur, LDIMC, 2);
    }

    // 5) write output
    int ncov = out_size > 1024 ? out_size : 1024;
    writeout_kernel<<<(ncov + 255) / 256, 256>>>(p_cur, out, out_size);
}

// round 4
// speedup vs baseline: 4.7711x; 1.4414x over previous
#include <cuda_runtime.h>
#include <cuda_bf16.h>
#include <math.h>
#include <stdint.h>

// ---------------- model constants ----------------
#define BDIM   8
#define TTXT   64
#define TSEQ   256
#define TTOT   320
#define MROWS  (BDIM*TTOT)    // 2560
#define DIM    1024
#define LDIMC  128
#define FFN    4096
#define HEADS  16
#define HDIM   64
#define NLAYER 4
#define HID    1024
#define KF1    1154
#define KP1    1160
#define NSTEPS 16

// ---------------- scratch ----------------
__device__ __align__(16) uint16_t g_seqb[BDIM*TSEQ*LDIMC];     // bf16 nanfixed seq
__device__ __align__(16) float    g_x   [BDIM*TSEQ*DIM];
__device__ __align__(16) float    g_h   [MROWS*DIM];
__device__ __align__(16) uint16_t g_tmpb[MROWS*DIM];           // bf16 LN out
__device__ __align__(16) float    g_qkv [MROWS*3*DIM];
__device__ __align__(16) uint16_t g_attb[MROWS*DIM];           // bf16 attn out
__device__ __align__(16) uint16_t g_midb[MROWS*FFN];           // bf16 gelu out
__device__ __align__(16) float    g_last[BDIM*DIM];
__device__ __align__(16) float    g_cur [BDIM*LDIMC];
__device__ __align__(16) float    g_f1  [BDIM*HID];
__device__ __align__(16) float    g_f2  [BDIM*HID];
__device__ __align__(16) float    g_p01 [2*MROWS*DIM];
// bf16 transposed weights  W^T [N][K]
__device__ __align__(16) uint16_t g_wint [DIM*LDIMC];
__device__ __align__(16) uint16_t g_wqkvt[NLAYER*3*DIM*DIM];
__device__ __align__(16) uint16_t g_wot  [NLAYER*DIM*DIM];
__device__ __align__(16) uint16_t g_w1t  [NLAYER*FFN*DIM];
__device__ __align__(16) uint16_t g_w2t  [NLAYER*DIM*FFN];
// fp32 transposed flow weights
__device__ __align__(16) float g_wf1t[HID*KP1];
__device__ __align__(16) float g_wf2t[HID*HID];
__device__ __align__(16) float g_wf3t[LDIMC*HID];
// grid barrier state
__device__ unsigned g_bar_cnt = 0;
__device__ unsigned g_bar_gen = 0;

// ---------------- helpers ----------------
__device__ __forceinline__ float gelu_tanh(float x) {
    const float c = 0.7978845608028654f;
    float t = c * (x + 0.044715f * x * x * x);
    return 0.5f * x * (1.0f + tanhf(t));
}
__device__ __forceinline__ float silu(float x) { return x / (1.0f + __expf(-x)); }
__device__ __forceinline__ uint32_t pack_bf2(float a, float b) {
    __nv_bfloat162 h2 = __floats2bfloat162_rn(a, b);
    return *(uint32_t*)&h2;
}
__device__ __forceinline__ uint16_t bf16u(float a) {
    __nv_bfloat16 h = __float2bfloat16_rn(a);
    return *(uint16_t*)&h;
}
__device__ __forceinline__ void cp_async16(void* smem_dst, const void* gmem_src) {
    uint32_t s = (uint32_t)__cvta_generic_to_shared(smem_dst);
    asm volatile("cp.async.cg.shared.global [%0], [%1], 16;\n" :: "r"(s), "l"(gmem_src));
}
__device__ __forceinline__ int swz(int c) { return c + (c >> 4); }

// ---------------- prep kernels ----------------
// dst[z][n][k] (bf16) = src[z][k][n] (fp32) ; K%64==0, N%32==0
__global__ void tconv_kernel(const float* __restrict__ src, uint16_t* __restrict__ dst,
                             int K, int N) {
    __shared__ float tile[32][65];   // [n][k]
    const float* s = src + (size_t)blockIdx.z * K * N;
    uint16_t* d    = dst + (size_t)blockIdx.z * K * N;
    int k0 = blockIdx.y * 64, n0 = blockIdx.x * 32;
    int tx = threadIdx.x, ty = threadIdx.y;   // (32,8)
    #pragma unroll
    for (int i = 0; i < 8; i++) {
        int kk = ty + i * 8;
        tile[tx][kk] = s[(size_t)(k0 + kk) * N + n0 + tx];
    }
    __syncthreads();
    #pragma unroll
    for (int i = 0; i < 4; i++) {
        int nn = ty + i * 8;
        uint32_t p = pack_bf2(tile[nn][2 * tx], tile[nn][2 * tx + 1]);
        *(uint32_t*)&d[(size_t)(n0 + nn) * K + k0 + 2 * tx] = p;
    }
}
__global__ void zero_kernel(float* __restrict__ p, int n) {
    int i = blockIdx.x * blockDim.x + threadIdx.x;
    if (i < n) p[i] = 0.f;
}
// dst[c*dstride + r] = src[r*C + c]  (fp32, flow weights)
__global__ void transpose_kernel(const float* __restrict__ src, float* __restrict__ dst,
                                 int R, int C, int dstride) {
    __shared__ float tile[32][33];
    int c0 = blockIdx.x * 32, r0 = blockIdx.y * 32;
    int tx = threadIdx.x, ty = threadIdx.y;
    #pragma unroll
    for (int i = 0; i < 4; i++) {
        int rr = r0 + ty + i * 8, cc = c0 + tx;
        if (rr < R && cc < C) tile[ty + i * 8][tx] = src[(size_t)rr * C + cc];
    }
    __syncthreads();
    #pragma unroll
    for (int i = 0; i < 4; i++) {
        int cc = c0 + ty + i * 8, rr = r0 + tx;
        if (cc < C && rr < R) dst[(size_t)cc * dstride + rr] = tile[tx][ty + i * 8];
    }
}

__global__ void nanfix_kernel(const float* __restrict__ seq,
                              const float* __restrict__ bos,
                              uint16_t* __restrict__ out, int n) {
    int i = blockIdx.x * blockDim.x + threadIdx.x;
    if (i < n) {
        float v = seq[i];
        v = (v != v) ? bos[i & (LDIMC - 1)] : v;
        out[i] = bf16u(v);
    }
}

__global__ void concat_kernel(const float* __restrict__ text,
                              const float* __restrict__ x,
                              float* __restrict__ h) {
    int idx = blockIdx.x * blockDim.x + threadIdx.x;
    int row = idx >> 8, c4 = idx & 255;
    if (row >= MROWS) return;
    int b = row / TTOT, t = row - b * TTOT;
    float4 v;
    if (t < TTXT)
        v = ((const float4*)text)[(size_t)(b * TTXT + t) * 256 + c4];
    else
        v = ((const float4*)x)[(size_t)(b * TSEQ + (t - TTXT)) * 256 + c4];
    ((float4*)h)[(size_t)row * 256 + c4] = v;
}

// ---------------- LayerNorm (fp32 in -> bf16 out) ----------------
__global__ void __launch_bounds__(256) ln_bf16_kernel(
        const float* __restrict__ in, uint16_t* __restrict__ out,
        const float* __restrict__ g, const float* __restrict__ bta) {
    int row = blockIdx.x, tid = threadIdx.x;
    float4 v = ((const float4*)(in + (size_t)row * DIM))[tid];
    float s  = v.x + v.y + v.z + v.w;
    float ss = v.x*v.x + v.y*v.y + v.z*v.z + v.w*v.w;
    #pragma unroll
    for (int o = 16; o; o >>= 1) {
        s  += __shfl_xor_sync(0xffffffffu, s,  o);
        ss += __shfl_xor_sync(0xffffffffu, ss, o);
    }
    __shared__ float sh[16];
    int w = tid >> 5, l = tid & 31;
    if (l == 0) { sh[w] = s; sh[8 + w] = ss; }
    __syncthreads();
    float S = 0.f, SS = 0.f;
    #pragma unroll
    for (int i = 0; i < 8; i++) { S += sh[i]; SS += sh[8 + i]; }
    float mean = S * (1.0f / DIM);
    float var  = SS * (1.0f / DIM) - mean * mean;
    float rs   = rsqrtf(var + 1e-5f);
    float4 gg = ((const float4*)g)[tid];
    float4 bb = ((const float4*)bta)[tid];
    uint2 o2;
    o2.x = pack_bf2((v.x - mean) * rs * gg.x + bb.x, (v.y - mean) * rs * gg.y + bb.y);
    o2.y = pack_bf2((v.z - mean) * rs * gg.z + bb.z, (v.w - mean) * rs * gg.w + bb.w);
    ((uint2*)(out + (size_t)row * DIM))[tid] = o2;
}

// ---------------- combine split-K partials + optional fused LN ----------------
__global__ void __launch_bounds__(256) combine_ln_kernel(
        const float* __restrict__ p0, const float* __restrict__ p1,
        const float* __restrict__ bias, float* __restrict__ h,
        const float* __restrict__ g, const float* __restrict__ bta,
        uint16_t* __restrict__ lnout, int do_ln) {
    int row = blockIdx.x, tid = threadIdx.x;
    size_t off = (size_t)row * DIM;
    float4 a  = ((const float4*)(p0 + off))[tid];
    float4 b4 = ((const float4*)(p1 + off))[tid];
    float4 r  = ((const float4*)(h + off))[tid];
    float4 bb = ((const float4*)bias)[tid];
    r.x += a.x + b4.x + bb.x;
    r.y += a.y + b4.y + bb.y;
    r.z += a.z + b4.z + bb.z;
    r.w += a.w + b4.w + bb.w;
    ((float4*)(h + off))[tid] = r;
    if (!do_ln) return;
    float s  = r.x + r.y + r.z + r.w;
    float ss = r.x*r.x + r.y*r.y + r.z*r.z + r.w*r.w;
    #pragma unroll
    for (int o = 16; o; o >>= 1) {
        s  += __shfl_xor_sync(0xffffffffu, s,  o);
        ss += __shfl_xor_sync(0xffffffffu, ss, o);
    }
    __shared__ float sh[16];
    int w = tid >> 5, l = tid & 31;
    if (l == 0) { sh[w] = s; sh[8 + w] = ss; }
    __syncthreads();
    float S = 0.f, SS = 0.f;
    #pragma unroll
    for (int i = 0; i < 8; i++) { S += sh[i]; SS += sh[8 + i]; }
    float mean = S * (1.0f / DIM);
    float var  = SS * (1.0f / DIM) - mean * mean;
    float rs   = rsqrtf(var + 1e-5f);
    float4 gg = ((const float4*)g)[tid];
    float4 b2 = ((const float4*)bta)[tid];
    uint2 o2;
    o2.x = pack_bf2((r.x - mean) * rs * gg.x + b2.x, (r.y - mean) * rs * gg.y + b2.y);
    o2.y = pack_bf2((r.z - mean) * rs * gg.z + b2.z, (r.w - mean) * rs * gg.w + b2.w);
    ((uint2*)(lnout + off))[tid] = o2;
}

// ---------------- bf16 tensor-core GEMM ----------------
// C[m][n] = epi( sum_k A[m][k]*Bt[n][k] + bias )
// A bf16 row-major [M][lda]; Bt bf16 [N][ldb] (W transposed)
// epi: 0 = bias->Cf ; 1 = bias+gelu->Cb(bf16) ; 3 = raw partial -> Cf + z*M*N
#define BKT 64
#define ASTR 72                       // bf16 elems per smem row
#define ATILE (128*ASTR)              // elems per stage
#define TG_SMEM (4*ATILE*2)           // bytes (A 2 stages + B 2 stages)

__global__ void __launch_bounds__(256, 2) tgemm_bf16(
        const uint16_t* __restrict__ A, int lda,
        const uint16_t* __restrict__ Bt, int ldb,
        const float* __restrict__ bias,
        float* __restrict__ Cf, uint16_t* __restrict__ Cb,
        int M, int N, int K, int epi) {
    extern __shared__ uint16_t smb[];
    uint16_t* As = smb;                 // [2][128][72]
    uint16_t* Bs = smb + 2 * ATILE;

    const int tid = threadIdx.x;
    const int bm = blockIdx.y * 128, bn = blockIdx.x * 128;
    const int koff = blockIdx.z * K;
    const int warp = tid >> 5, lane = tid & 31;
    const int wm = (warp & 3) * 32;
    const int wn = (warp >> 2) * 64;
    const int g  = lane >> 2, t = lane & 3;

    const uint16_t* Ab0 = A  + (size_t)bm * lda + koff;
    const uint16_t* Bb0 = Bt + (size_t)bn * ldb + koff;

    auto loadStage = [&](int kt, int stage) {
        #pragma unroll
        for (int i = 0; i < 4; i++) {
            int idx = tid + i * 256;
            int r = idx >> 3, c = idx & 7;
            cp_async16(As + stage * ATILE + r * ASTR + c * 8,
                       Ab0 + (size_t)r * lda + kt * BKT + c * 8);
            cp_async16(Bs + stage * ATILE + r * ASTR + c * 8,
                       Bb0 + (size_t)r * ldb + kt * BKT + c * 8);
        }
        asm volatile("cp.async.commit_group;\n" ::);
    };

    float acc[2][8][4];
    #pragma unroll
    for (int i = 0; i < 2; i++)
        #pragma unroll
        for (int j = 0; j < 8; j++)
            #pragma unroll
            for (int q = 0; q < 4; q++) acc[i][j][q] = 0.f;

    const int nk = K / BKT;
    loadStage(0, 0);

    for (int kt = 0; kt < nk; kt++) {
        if (kt + 1 < nk) {
            loadStage(kt + 1, (kt + 1) & 1);
            asm volatile("cp.async.wait_group 1;\n" ::);
        } else {
            asm volatile("cp.async.wait_group 0;\n" ::);
        }
        __syncthreads();

        const uint32_t* A32 = (const uint32_t*)(As + (kt & 1) * ATILE);
        const uint32_t* B32 = (const uint32_t*)(Bs + (kt & 1) * ATILE);

        #pragma unroll
        for (int ks = 0; ks < 4; ks++) {
            const int kb = ks * 8;     // word offset within row (36 words/row)
            uint32_t af[2][4], bf[8][2];
            #pragma unroll
            for (int mt = 0; mt < 2; mt++) {
                int m0 = wm + mt * 16 + g;
                af[mt][0] = A32[m0 * 36 + kb + t];
                af[mt][1] = A32[(m0 + 8) * 36 + kb + t];
                af[mt][2] = A32[m0 * 36 + kb + t + 4];
                af[mt][3] = A32[(m0 + 8) * 36 + kb + t + 4];
            }
            #pragma unroll
            for (int nt = 0; nt < 8; nt++) {
                int n0 = wn + nt * 8 + g;
                bf[nt][0] = B32[n0 * 36 + kb + t];
                bf[nt][1] = B32[n0 * 36 + kb + t + 4];
            }
            #pragma unroll
            for (int mt = 0; mt < 2; mt++)
                #pragma unroll
                for (int nt = 0; nt < 8; nt++) {
                    asm volatile(
                        "mma.sync.aligned.m16n8k16.row.col.f32.bf16.bf16.f32 "
                        "{%0,%1,%2,%3}, {%4,%5,%6,%7}, {%8,%9}, {%0,%1,%2,%3};\n"
                        : "+f"(acc[mt][nt][0]), "+f"(acc[mt][nt][1]),
                          "+f"(acc[mt][nt][2]), "+f"(acc[mt][nt][3])
                        : "r"(af[mt][0]), "r"(af[mt][1]), "r"(af[mt][2]), "r"(af[mt][3]),
                          "r"(bf[nt][0]), "r"(bf[nt][1]));
                }
        }
        __syncthreads();
    }

    float* Cout = (epi == 3) ? (Cf + (size_t)blockIdx.z * M * N) : Cf;
    #pragma unroll
    for (int mt = 0; mt < 2; mt++) {
        #pragma unroll
        for (int nt = 0; nt < 8; nt++) {
            int c = bn + wn + nt * 8 + t * 2;
            float bx = 0.f, by = 0.f;
            if (epi != 3) { bx = bias[c]; by = bias[c + 1]; }
            #pragma unroll
            for (int rr = 0; rr < 2; rr++) {
                int gm = bm + wm + mt * 16 + g + rr * 8;
                size_t off = (size_t)gm * N + c;
                float vx = acc[mt][nt][rr * 2 + 0] + bx;
                float vy = acc[mt][nt][rr * 2 + 1] + by;
                if (epi == 1) {
                    *(uint32_t*)&Cb[off] = pack_bf2(gelu_tanh(vx), gelu_tanh(vy));
                } else {
                    *(float2*)&Cout[off] = make_float2(vx, vy);
                }
            }
        }
    }
}

// ---------------- causal attention (fp32 in, bf16 out) ----------------
__global__ void __launch_bounds__(256) attn_kernel(
        const float* __restrict__ qkv, uint16_t* __restrict__ o) {
    const int qt = blockIdx.x, hh = blockIdx.y, b = blockIdx.z;
    const int tid = threadIdx.x;
    const int ql = tid >> 2, part = tid & 3;
    const int q  = qt * 64 + ql;

    __shared__ float Ks[64 * 68];
    __shared__ float Vs[64 * 68];

    float qreg[16], acc[16];
    const float* qp = qkv + (size_t)(b * TTOT + q) * (3 * DIM) + hh * HDIM + part * 16;
    #pragma unroll
    for (int i = 0; i < 4; i++) {
        float4 v = ((const float4*)qp)[i];
        qreg[4*i+0] = v.x; qreg[4*i+1] = v.y; qreg[4*i+2] = v.z; qreg[4*i+3] = v.w;
    }
    #pragma unroll
    for (int d = 0; d < 16; d++) acc[d] = 0.f;
    float mrun = -1e30f, lrun = 0.f;

    const int nkt = qt + 1;
    for (int kt = 0; kt < nkt; kt++) {
        {
            int r = tid >> 2, c = (tid & 3) * 16;
            const float* kp = qkv + (size_t)(b * TTOT + kt * 64 + r) * (3 * DIM)
                              + DIM + hh * HDIM + c;
            const float* vp = kp + DIM;
            #pragma unroll
            for (int i = 0; i < 4; i++) {
                float4 kv = ((const float4*)kp)[i];
                float4 vv = ((const float4*)vp)[i];
                int cb = c + i * 4;
                Ks[r * 68 + swz(cb+0)] = kv.x; Ks[r * 68 + swz(cb+1)] = kv.y;
                Ks[r * 68 + swz(cb+2)] = kv.z; Ks[r * 68 + swz(cb+3)] = kv.w;
                Vs[r * 68 + swz(cb+0)] = vv.x; Vs[r * 68 + swz(cb+1)] = vv.y;
                Vs[r * 68 + swz(cb+2)] = vv.z; Vs[r * 68 + swz(cb+3)] = vv.w;
            }
        }
        __syncthreads();

        const int pbase = part * 17;
        for (int j = 0; j < 64; j++) {
            const float* kr = &Ks[j * 68 + pbase];
            float s = 0.f;
            #pragma unroll
            for (int d = 0; d < 16; d++) s = fmaf(qreg[d], kr[d], s);
            s += __shfl_xor_sync(0xffffffffu, s, 1);
            s += __shfl_xor_sync(0xffffffffu, s, 2);
            s *= 0.125f;
            int kg = kt * 64 + j;
            s = (kg <= q) ? s : -1e30f;
            if (s > mrun) {
                float corr = __expf(mrun - s);
                lrun *= corr;
                #pragma unroll
                for (int d = 0; d < 16; d++) acc[d] *= corr;
                mrun = s;
            }
            float p = __expf(s - mrun);
            lrun += p;
            const float* vr = &Vs[j * 68 + pbase];
            #pragma unroll
            for (int d = 0; d < 16; d++) acc[d] = fmaf(p, vr[d], acc[d]);
        }
        __syncthreads();
    }

    float inv = 1.0f / lrun;
    uint16_t* op = o + (size_t)(b * TTOT + q) * DIM + hh * HDIM + part * 16;
    uint4 u0, u1;
    u0.x = pack_bf2(acc[0]*inv,  acc[1]*inv);  u0.y = pack_bf2(acc[2]*inv,  acc[3]*inv);
    u0.z = pack_bf2(acc[4]*inv,  acc[5]*inv);  u0.w = pack_bf2(acc[6]*inv,  acc[7]*inv);
    u1.x = pack_bf2(acc[8]*inv,  acc[9]*inv);  u1.y = pack_bf2(acc[10]*inv, acc[11]*inv);
    u1.z = pack_bf2(acc[12]*inv, acc[13]*inv); u1.w = pack_bf2(acc[14]*inv, acc[15]*inv);
    ((uint4*)op)[0] = u0;
    ((uint4*)op)[1] = u1;
}

// ---------------- finalize: fp32 LN of last tokens + eos + cur init ----------------
__global__ void __launch_bounds__(256) finalize_kernel(
        const float* __restrict__ h, const float* __restrict__ noise,
        const float* __restrict__ ong, const float* __restrict__ onb,
        const float* __restrict__ Weos, const float* __restrict__ beos,
        float* __restrict__ last, float* __restrict__ cur,
        float* __restrict__ out, int out_size) {
    int b = blockIdx.x, tid = threadIdx.x;
    float4 v = ((const float4*)(h + (size_t)(b * TTOT + TTOT - 1) * DIM))[tid];
    float s  = v.x + v.y + v.z + v.w;
    float ss = v.x*v.x + v.y*v.y + v.z*v.z + v.w*v.w;
    #pragma unroll
    for (int o = 16; o; o >>= 1) {
        s  += __shfl_xor_sync(0xffffffffu, s,  o);
        ss += __shfl_xor_sync(0xffffffffu, ss, o);
    }
    __shared__ float sh[16];
    int w = tid >> 5, l = tid & 31;
    if (l == 0) { sh[w] = s; sh[8 + w] = ss; }
    __syncthreads();
    float S = 0.f, SS = 0.f;
    #pragma unroll
    for (int i = 0; i < 8; i++) { S += sh[i]; SS += sh[8 + i]; }
    float mean = S * (1.0f / DIM);
    float var  = SS * (1.0f / DIM) - mean * mean;
    float rs   = rsqrtf(var + 1e-5f);
    float4 gg = ((const float4*)ong)[tid];
    float4 bb = ((const float4*)onb)[tid];
    float4 nv;
    nv.x = (v.x - mean) * rs * gg.x + bb.x;
    nv.y = (v.y - mean) * rs * gg.y + bb.y;
    nv.z = (v.z - mean) * rs * gg.z + bb.z;
    nv.w = (v.w - mean) * rs * gg.w + bb.w;
    ((float4*)(last + (size_t)b * DIM))[tid] = nv;
    float4 we = ((const float4*)Weos)[tid];
    float p = nv.x*we.x + nv.y*we.y + nv.z*we.z + nv.w*we.w;
    __shared__ float red[256];
    red[tid] = p;
    __syncthreads();
    for (int st = 128; st; st >>= 1) {
        if (tid < st) red[tid] += red[tid + st];
        __syncthreads();
    }
    if (tid == 0 && (1024 + b) < out_size) {
        float e = red[0] + beos[0];
        out[1024 + b] = (e > 0.5f) ? 1.0f : 0.0f;
    }
    if (tid < LDIMC) cur[b * LDIMC + tid] = noise[b * LDIMC + tid];
}

// ---------------- persistent flow decoder ----------------
#define FLOW_BLOCKS 128
#define FLOW_SMEM ((8*KP1 + 8*HID)*4)

__device__ __forceinline__ void gbar(unsigned expect) {
    __syncthreads();
    if (threadIdx.x == 0) {
        __threadfence();
        unsigned a = atomicAdd(&g_bar_cnt, 1u);
        if (a == FLOW_BLOCKS - 1) {
            atomicExch(&g_bar_cnt, 0u);
            __threadfence();
            atomicAdd(&g_bar_gen, 1u);
        } else {
            while (*((volatile unsigned*)&g_bar_gen) != expect) { }
            __threadfence();
        }
    }
    __syncthreads();
}

__global__ void __launch_bounds__(256) flow_all_kernel(
        const float* __restrict__ last, float* __restrict__ cur,
        const float* __restrict__ Wf1t, const float* __restrict__ bf1,
        const float* __restrict__ Wf2t, const float* __restrict__ bf2,
        const float* __restrict__ Wf3t, const float* __restrict__ bf3,
        float* __restrict__ f1, float* __restrict__ f2) {
    extern __shared__ float shf[];
    float* xs1 = shf;             // [8][KP1]
    float* xs2 = shf + 8 * KP1;   // [8][HID]
    const int tid = threadIdx.x, blk = blockIdx.x;
    const int warp = tid >> 5, lane = tid & 31;

    unsigned gen0 = *((volatile unsigned*)&g_bar_gen);
    unsigned bc = 0;

    // load last (persists across steps) + zero pad
    for (int i = tid; i < 8 * 1024; i += 256) {
        int m = i >> 10, k = i & 1023;
        xs1[m * KP1 + k] = last[m * 1024 + k];
    }
    if (tid < 48) {
        int m = tid / 6, k = KF1 + tid % 6;
        xs1[m * KP1 + k] = 0.f;
    }

    for (int step = 0; step < NSTEPS; step++) {
        float sv = (float)step / NSTEPS;
        float tv = (float)(step + 1) / NSTEPS;
        // update s,t,cur region of xs1
        for (int i = tid; i < 8 * LDIMC; i += 256) {
            int m = i >> 7, k = i & 127;
            xs1[m * KP1 + 1026 + k] = cur[i];
        }
        if (tid < 16) {
            int m = tid >> 1;
            xs1[m * KP1 + 1024 + (tid & 1)] = (tid & 1) ? tv : sv;
        }
        __syncthreads();

        // phase 1: f1 = silu(inp @ Wf1 + bf1)
        {
            int n = blk * 8 + warp;
            const float* wp = Wf1t + (size_t)n * KP1;
            float acc[8] = {0,0,0,0,0,0,0,0};
            for (int k0 = lane * 4; k0 < KP1; k0 += 128) {
                float4 w4 = *(const float4*)&wp[k0];
                #pragma unroll
                for (int m = 0; m < 8; m++) {
                    float4 x4 = *(const float4*)&xs1[m * KP1 + k0];
                    acc[m] += w4.x*x4.x + w4.y*x4.y + w4.z*x4.z + w4.w*x4.w;
                }
            }
            #pragma unroll
            for (int m = 0; m < 8; m++) {
                float v = acc[m];
                #pragma unroll
                for (int o2 = 16; o2; o2 >>= 1) v += __shfl_xor_sync(0xffffffffu, v, o2);
                acc[m] = v;
            }
            if (lane == 0) {
                float bn = bf1[n];
                #pragma unroll
                for (int m = 0; m < 8; m++) f1[m * HID + n] = silu(acc[m] + bn);
            }
        }
        gbar(gen0 + ++bc);

        // phase 2: f2 = silu(f1 @ Wf2 + bf2)
        for (int i = tid * 4; i < 8 * HID; i += 1024)
            *(float4*)&xs2[i] = *(const float4*)&f1[i];
        __syncthreads();
        {
            int n = blk * 8 + warp;
            const float* wp = Wf2t + (size_t)n * HID;
            float acc[8] = {0,0,0,0,0,0,0,0};
            for (int k0 = lane * 4; k0 < HID; k0 += 128) {
                float4 w4 = *(const float4*)&wp[k0];
                #pragma unroll
                for (int m = 0; m < 8; m++) {
                    float4 x4 = *(const float4*)&xs2[m * HID + k0];
                    acc[m] += w4.x*x4.x + w4.y*x4.y + w4.z*x4.z + w4.w*x4.w;
                }
            }
            #pragma unroll
            for (int m = 0; m < 8; m++) {
                float v = acc[m];
                #pragma unroll
                for (int o2 = 16; o2; o2 >>= 1) v += __shfl_xor_sync(0xffffffffu, v, o2);
                acc[m] = v;
            }
            if (lane == 0) {
                float bn = bf2[n];
                #pragma unroll
                for (int m = 0; m < 8; m++) f2[m * HID + n] = silu(acc[m] + bn);
            }
        }
        gbar(gen0 + ++bc);

        // phase 3: cur += (f2 @ Wf3 + bf3)/NSTEPS  (blocks 0..15)
        if (blk < 16) {
            for (int i = tid * 4; i < 8 * HID; i += 1024)
                *(float4*)&xs2[i] = *(const float4*)&f2[i];
            __syncthreads();
            int n = blk * 8 + warp;
            const float* wp = Wf3t + (size_t)n * HID;
            float acc[8] = {0,0,0,0,0,0,0,0};
            for (int k0 = lane * 4; k0 < HID; k0 += 128) {
                float4 w4 = *(const float4*)&wp[k0];
                #pragma unroll
                for (int m = 0; m < 8; m++) {
                    float4 x4 = *(const float4*)&xs2[m * HID + k0];
                    acc[m] += w4.x*x4.x + w4.y*x4.y + w4.z*x4.z + w4.w*x4.w;
                }
            }
            #pragma unroll
            for (int m = 0; m < 8; m++) {
                float v = acc[m];
                #pragma unroll
                for (int o2 = 16; o2; o2 >>= 1) v += __shfl_xor_sync(0xffffffffu, v, o2);
                acc[m] = v;
            }
            if (lane == 0) {
                float bn = bf3[n];
                #pragma unroll
                for (int m = 0; m < 8; m++)
                    cur[m * LDIMC + n] += (acc[m] + bn) * (1.0f / NSTEPS);
            }
        }
        gbar(gen0 + ++bc);
    }
}

__global__ void writeout_kernel(const float* __restrict__ cur,
                                float* __restrict__ out, int out_size) {
    int i = blockIdx.x * blockDim.x + threadIdx.x;
    if (i >= out_size) return;
    if (i < 1024)       out[i] = cur[i];
    else if (i >= 1032) out[i] = 0.0f;
}

// ---------------- host orchestration ----------------
extern "C" void kernel_launch(void* const* d_in, const int* in_sizes, int n_in,
                              void* d_out, int out_size) {
    const float* seq   = (const float*)d_in[0];
    const float* text  = (const float*)d_in[1];
    const float* noise = (const float*)d_in[2];
    const float* bos   = (const float*)d_in[4];
    const float* W_in  = (const float*)d_in[5];
    const float* b_in  = (const float*)d_in[6];
    const float* ln1g  = (const float*)d_in[7];
    const float* ln1b  = (const float*)d_in[8];
    const float* Wqkv  = (const float*)d_in[9];
    const float* bqkv  = (const float*)d_in[10];
    const float* Wo    = (const float*)d_in[11];
    const float* bo    = (const float*)d_in[12];
    const float* ln2g  = (const float*)d_in[13];
    const float* ln2b  = (const float*)d_in[14];
    const float* W1    = (const float*)d_in[15];
    const float* b1    = (const float*)d_in[16];
    const float* W2    = (const float*)d_in[17];
    const float* b2    = (const float*)d_in[18];
    const float* ong   = (const float*)d_in[19];
    const float* onb   = (const float*)d_in[20];
    const float* Weos  = (const float*)d_in[21];
    const float* beos  = (const float*)d_in[22];
    const float* Wf1   = (const float*)d_in[23];
    const float* bf1   = (const float*)d_in[24];
    const float* Wf2   = (const float*)d_in[25];
    const float* bf2   = (const float*)d_in[26];
    const float* Wf3   = (const float*)d_in[27];
    const float* bf3   = (const float*)d_in[28];
    float* out = (float*)d_out;

    uint16_t *p_seqb, *p_tmpb, *p_attb, *p_midb;
    uint16_t *p_wint, *p_wqkvt, *p_wot, *p_w1t, *p_w2t;
    float *p_x, *p_h, *p_qkv, *p_last, *p_cur, *p_f1, *p_f2, *p_p01;
    float *p_wf1t, *p_wf2t, *p_wf3t;
    cudaGetSymbolAddress((void**)&p_seqb,  g_seqb);
    cudaGetSymbolAddress((void**)&p_tmpb,  g_tmpb);
    cudaGetSymbolAddress((void**)&p_attb,  g_attb);
    cudaGetSymbolAddress((void**)&p_midb,  g_midb);
    cudaGetSymbolAddress((void**)&p_wint,  g_wint);
    cudaGetSymbolAddress((void**)&p_wqkvt, g_wqkvt);
    cudaGetSymbolAddress((void**)&p_wot,   g_wot);
    cudaGetSymbolAddress((void**)&p_w1t,   g_w1t);
    cudaGetSymbolAddress((void**)&p_w2t,   g_w2t);
    cudaGetSymbolAddress((void**)&p_x,     g_x);
    cudaGetSymbolAddress((void**)&p_h,     g_h);
    cudaGetSymbolAddress((void**)&p_qkv,   g_qkv);
    cudaGetSymbolAddress((void**)&p_last,  g_last);
    cudaGetSymbolAddress((void**)&p_cur,   g_cur);
    cudaGetSymbolAddress((void**)&p_f1,    g_f1);
    cudaGetSymbolAddress((void**)&p_f2,    g_f2);
    cudaGetSymbolAddress((void**)&p_p01,   g_p01);
    cudaGetSymbolAddress((void**)&p_wf1t,  g_wf1t);
    cudaGetSymbolAddress((void**)&p_wf2t,  g_wf2t);
    cudaGetSymbolAddress((void**)&p_wf3t,  g_wf3t);

    cudaFuncSetAttribute(tgemm_bf16,
                         cudaFuncAttributeMaxDynamicSharedMemorySize, TG_SMEM);
    cudaFuncSetAttribute(flow_all_kernel,
                         cudaFuncAttributeMaxDynamicSharedMemorySize, FLOW_SMEM);

    // 0) weight prep: transpose + convert to bf16 ; flow weights transpose fp32
    dim3 tb(32, 8);
    tconv_kernel<<<dim3(DIM/32,  LDIMC/64, 1),      tb>>>(W_in, p_wint,  LDIMC, DIM);
    tconv_kernel<<<dim3(3*DIM/32, DIM/64, NLAYER),  tb>>>(Wqkv, p_wqkvt, DIM, 3*DIM);
    tconv_kernel<<<dim3(DIM/32,  DIM/64, NLAYER),   tb>>>(Wo,   p_wot,   DIM, DIM);
    tconv_kernel<<<dim3(FFN/32,  DIM/64, NLAYER),   tb>>>(W1,   p_w1t,   DIM, FFN);
    tconv_kernel<<<dim3(DIM/32,  FFN/64, NLAYER),   tb>>>(W2,   p_w2t,   FFN, DIM);
    zero_kernel<<<(HID*KP1 + 255)/256, 256>>>(p_wf1t, HID*KP1);
    transpose_kernel<<<dim3((HID+31)/32, (KF1+31)/32), tb>>>(Wf1, p_wf1t, KF1, HID, KP1);
    transpose_kernel<<<dim3((HID+31)/32, (HID+31)/32), tb>>>(Wf2, p_wf2t, HID, HID, HID);
    transpose_kernel<<<dim3((LDIMC+31)/32, (HID+31)/32), tb>>>(Wf3, p_wf3t, HID, LDIMC, HID);

    // 1) input path
    int nseq = BDIM * TSEQ * LDIMC;
    nanfix_kernel<<<(nseq + 255)/256, 256>>>(seq, bos, p_seqb, nseq);
    tgemm_bf16<<<dim3(DIM/128, (BDIM*TSEQ)/128, 1), 256, TG_SMEM>>>(
        p_seqb, LDIMC, p_wint, LDIMC, b_in, p_x, nullptr, BDIM*TSEQ, DIM, LDIMC, 0);
    concat_kernel<<<(MROWS*256 + 255)/256, 256>>>(text, p_x, p_h);
    ln_bf16_kernel<<<MROWS, 256>>>(p_h, p_tmpb, ln1g, ln1b);

    // 2) transformer layers
    for (int l = 0; l < NLAYER; l++) {
        tgemm_bf16<<<dim3(3*DIM/128, MROWS/128, 1), 256, TG_SMEM>>>(
            p_tmpb, DIM, p_wqkvt + (size_t)l*3*DIM*DIM, DIM,
            bqkv + l*3*DIM, p_qkv, nullptr, MROWS, 3*DIM, DIM, 0);
        attn_kernel<<<dim3(TTOT/64, HEADS, BDIM), 256>>>(p_qkv, p_attb);
        tgemm_bf16<<<dim3(DIM/128, MROWS/128, 2), 256, TG_SMEM>>>(
            p_attb, DIM, p_wot + (size_t)l*DIM*DIM, DIM,
            nullptr, p_p01, nullptr, MROWS, DIM, 512, 3);
        combine_ln_kernel<<<MROWS, 256>>>(
            p_p01, p_p01 + (size_t)MROWS*DIM, bo + l*DIM, p_h,
            ln2g + l*DIM, ln2b + l*DIM, p_tmpb, 1);
        tgemm_bf16<<<dim3(FFN/128, MROWS/128, 1), 256, TG_SMEM>>>(
            p_tmpb, DIM, p_w1t + (size_t)l*FFN*DIM, DIM,
            b1 + l*FFN, nullptr, p_midb, MROWS, FFN, DIM, 1);
        tgemm_bf16<<<dim3(DIM/128, MROWS/128, 2), 256, TG_SMEM>>>(
            p_midb, FFN, p_w2t + (size_t)l*DIM*FFN, FFN,
            nullptr, p_p01, nullptr, MROWS, DIM, 2048, 3);
        if (l < NLAYER - 1) {
            combine_ln_kernel<<<MROWS, 256>>>(
                p_p01, p_p01 + (size_t)MROWS*DIM, b2 + l*DIM, p_h,
                ln1g + (l+1)*DIM, ln1b + (l+1)*DIM, p_tmpb, 1);
        } else {
            combine_ln_kernel<<<MROWS, 256>>>(
                p_p01, p_p01 + (size_t)MROWS*DIM, b2 + l*DIM, p_h,
                nullptr, nullptr, nullptr, 0);
        }
    }

    // 3) finalize: fp32 LN on last tokens only + eos + cur init
    finalize_kernel<<<BDIM, 256>>>(p_h, noise, ong, onb, Weos, beos,
                                   p_last, p_cur, out, out_size);

    // 4) persistent flow decoder (one launch, software grid barriers)
    flow_all_kernel<<<FLOW_BLOCKS, 256, FLOW_SMEM>>>(
        p_last, p_cur, p_wf1t, bf1, p_wf2t, bf2, p_wf3t, bf3, p_f1, p_f2);

    // 5) write output
    int ncov = out_size > 1024 ? out_size : 1024;
    writeout_kernel<<<(ncov + 255)/256, 256>>>(p_cur, out, out_size);
}